// round 6
// baseline (speedup 1.0000x reference)
#include <cuda_runtime.h>
#include <cuda_bf16.h>
#include <math.h>
#include <stdint.h>

// ---------------- problem constants ----------------
#define BWIN   2048
#define NTOK   64
#define CHANS  512
#define NHEAD  16
#define HDIM   32
#define NWMASK 256
#define MROWS  (BWIN * NTOK)     // 131072
#define QKVN   (3 * CHANS)       // 1536
#define LOGMAX 4.6051701859880914f

// ---------------- scratch ----------------
__device__ float g_qkv[(size_t)MROWS * QKVN];
__device__ __nv_bfloat16 g_x_hi[(size_t)MROWS * CHANS];
__device__ __nv_bfloat16 g_x_lo[(size_t)MROWS * CHANS];
__device__ __nv_bfloat16 g_ao_hi[(size_t)MROWS * CHANS];
__device__ __nv_bfloat16 g_ao_lo[(size_t)MROWS * CHANS];
__device__ __nv_bfloat16 g_wq_hi[(size_t)QKVN * CHANS];   // [N,K] transposed
__device__ __nv_bfloat16 g_wq_lo[(size_t)QKVN * CHANS];
__device__ __nv_bfloat16 g_wp_hi[(size_t)CHANS * CHANS];
__device__ __nv_bfloat16 g_wp_lo[(size_t)CHANS * CHANS];
__device__ float g_table[225 * NHEAD];
__device__ float g_bias[NHEAD * NTOK * NTOK];
__device__ float g_qkv_bias[QKVN];

// ---------------- helpers ----------------
__device__ __forceinline__ uint32_t smem_u32(const void* p) {
    uint32_t a;
    asm("{ .reg .u64 t; cvta.to.shared.u64 t, %1; cvt.u32.u64 %0, t; }" : "=r"(a) : "l"(p));
    return a;
}
__device__ __forceinline__ void cp16(uint32_t dst, const void* src) {
    asm volatile("cp.async.cg.shared.global [%0], [%1], 16;" :: "r"(dst), "l"(src));
}
#define CP_COMMIT() asm volatile("cp.async.commit_group;" ::: "memory")
__device__ __forceinline__ void cp_wait(int rem) {
    if (rem >= 2)      asm volatile("cp.async.wait_group 2;" ::: "memory");
    else if (rem == 1) asm volatile("cp.async.wait_group 1;" ::: "memory");
    else               asm volatile("cp.async.wait_group 0;" ::: "memory");
}
__device__ __forceinline__ void ldm_x4(uint32_t* r, uint32_t addr) {
    asm volatile("ldmatrix.sync.aligned.m8n8.x4.shared.b16 {%0,%1,%2,%3}, [%4];"
                 : "=r"(r[0]), "=r"(r[1]), "=r"(r[2]), "=r"(r[3]) : "r"(addr));
}
__device__ __forceinline__ void mma_bf16(float* d, const uint32_t* a, uint32_t b0, uint32_t b1) {
    asm volatile(
        "mma.sync.aligned.m16n8k16.row.col.f32.bf16.bf16.f32 "
        "{%0,%1,%2,%3}, {%4,%5,%6,%7}, {%8,%9}, {%0,%1,%2,%3};"
        : "+f"(d[0]), "+f"(d[1]), "+f"(d[2]), "+f"(d[3])
        : "r"(a[0]), "r"(a[1]), "r"(a[2]), "r"(a[3]), "r"(b0), "r"(b1));
}
__device__ __forceinline__ void split1(float x, __nv_bfloat16& h, __nv_bfloat16& l) {
    h = __float2bfloat16(x);
    l = __float2bfloat16(x - __bfloat162float(h));
}
// packed f32x2 FMA (Blackwell FFMA2, PTX-only)
__device__ __forceinline__ void ffma2(unsigned long long& d,
                                      unsigned long long a, unsigned long long b) {
    asm("fma.rn.f32x2 %0, %1, %2, %0;" : "+l"(d) : "l"(a), "l"(b));
}
__device__ __forceinline__ unsigned long long pack2(float x, float y) {
    unsigned long long r;
    asm("mov.b64 %0, {%1, %2};" : "=l"(r) : "f"(x), "f"(y));
    return r;
}
__device__ __forceinline__ void unpack2(unsigned long long v, float& x, float& y) {
    asm("mov.b64 {%0, %1}, %2;" : "=f"(x), "=f"(y) : "l"(v));
}
// fast exp via FMA polynomial (no MUFU)
__device__ __forceinline__ float fexp(float x) {
    float t = fmaxf(x * 1.442695040888963f, -125.f);
    float n = rintf(t);
    float f = t - n;
    float p = 1.3392138e-3f;
    p = fmaf(p, f, 9.6181291e-3f);
    p = fmaf(p, f, 5.5504108e-2f);
    p = fmaf(p, f, 2.4022650e-1f);
    p = fmaf(p, f, 6.9314718e-1f);
    p = fmaf(p, f, 1.0f);
    return __int_as_float(((int)n + 127) << 23) * p;
}

// ---------------- tiny prep kernels ----------------
__global__ void qkvbias_kernel(const float* __restrict__ qb,
                               const float* __restrict__ vb) {
    int n = blockIdx.x * 256 + threadIdx.x;
    if (n >= QKVN) return;
    float v = 0.f;
    if (n < CHANS) v = qb[n];
    else if (n >= 2 * CHANS) v = vb[n - 2 * CHANS];
    g_qkv_bias[n] = v;
}

__global__ void cpb_table_kernel(const float* __restrict__ rel_table,
                                 const float* __restrict__ w1,
                                 const float* __restrict__ b1,
                                 const float* __restrict__ w2) {
    int p = blockIdx.x;
    int j = threadIdx.x;
    __shared__ float hid[512];
    float t0 = rel_table[p * 2 + 0];
    float t1 = rel_table[p * 2 + 1];
    hid[j] = fmaxf(t0 * w1[j] + t1 * w1[512 + j] + b1[j], 0.f);
    __syncthreads();
    if (j < NHEAD) {
        float acc = 0.f;
        #pragma unroll 8
        for (int r = 0; r < 512; ++r) acc += hid[r] * w2[r * NHEAD + j];
        g_table[p * NHEAD + j] = acc;
    }
}

__global__ void bias_expand_kernel() {
    int id = blockIdx.x * 256 + threadIdx.x;
    int h = id >> 12;
    int i = (id >> 6) & 63;
    int j = id & 63;
    int idx = ((i >> 3) - (j >> 3) + 7) * 15 + ((i & 7) - (j & 7) + 7);
    float b = g_table[idx * NHEAD + h];
    g_bias[id] = 16.f / (1.f + fexp(-b));
}

__global__ void split_x_kernel(const float* __restrict__ src) {
    size_t i = ((size_t)blockIdx.x * 256 + threadIdx.x) * 4;
    float4 v = *(const float4*)&src[i];
    __align__(8) __nv_bfloat16 h[4], l[4];
    split1(v.x, h[0], l[0]);
    split1(v.y, h[1], l[1]);
    split1(v.z, h[2], l[2]);
    split1(v.w, h[3], l[3]);
    *(uint2*)&g_x_hi[i] = *(uint2*)h;
    *(uint2*)&g_x_lo[i] = *(uint2*)l;
}

__global__ void wsplit_kernel(const float* __restrict__ w,
                              __nv_bfloat16* __restrict__ hiT,
                              __nv_bfloat16* __restrict__ loT,
                              int K, int N) {
    int idx = blockIdx.x * 256 + threadIdx.x;
    if (idx >= K * N) return;
    int k = idx / N, n = idx % N;
    __nv_bfloat16 h, l;
    split1(w[idx], h, l);
    hiT[(size_t)n * K + k] = h;
    loT[(size_t)n * K + k] = l;
}

// ---------------- HMMA bf16x3 GEMM ----------------
// BM=128 BN=128 BK=32, 128 threads / 4 warps (2Mx2N), warp tile 64x64,
// 3-stage cp.async pipeline (96KB smem, 2 CTAs/SM).
#define PITCH 40
#define TILE_B (128 * PITCH * 2)         // 10240 B
#define STAGE_B (4 * TILE_B)             // 40960 B
#define NSTAGE 3
#define GEMM_SMEM (NSTAGE * STAGE_B)     // 122880? no: 3*40960 = 122880 B

__global__ void __launch_bounds__(128, 1)
hmma_gemm(const __nv_bfloat16* __restrict__ Ahi, const __nv_bfloat16* __restrict__ Alo,
          const __nv_bfloat16* __restrict__ Bhi, const __nv_bfloat16* __restrict__ Blo,
          const float* __restrict__ bias, float* __restrict__ C,
          int M, int N, int K) {
    extern __shared__ char smem[];
    const uint32_t sb = smem_u32(smem);
    const int tid = threadIdx.x;
    const int wid = tid >> 5, lane = tid & 31;
    const int bm = blockIdx.y * 128;
    const int bn = blockIdx.x * 128;
    const int wm = (wid >> 1) * 64;
    const int wn = (wid & 1) * 64;
    const int nch = K >> 5;

    auto load_tile = [&](const __nv_bfloat16* g, int rowbase, int k0, uint32_t off) {
        #pragma unroll
        for (int c = tid; c < 512; c += 128) {
            int row = c >> 2, chunk = c & 3;
            cp16(sb + off + row * (PITCH * 2) + chunk * 16,
                 g + (size_t)(rowbase + row) * K + k0 + chunk * 8);
        }
    };
    auto load_chunk = [&](int chunk) {
        int k0 = chunk << 5;
        uint32_t s0 = (uint32_t)(chunk % NSTAGE) * STAGE_B;
        load_tile(Ahi, bm, k0, s0);
        load_tile(Alo, bm, k0, s0 + TILE_B);
        load_tile(Bhi, bn, k0, s0 + 2 * TILE_B);
        load_tile(Blo, bn, k0, s0 + 3 * TILE_B);
        CP_COMMIT();
    };

    float acc[4][8][4] = {};   // [mi][nj][reg], warp tile 64x64

    load_chunk(0);
    if (nch > 1) load_chunk(1);

    const int lt = lane >> 3;
    const int lr = lane & 7;
    const int a_row_in = ((lt & 1) << 3) + lr;
    const int a_k16 = lt >> 1;
    const int b_n_in = ((lt >> 1) << 3) + lr;
    const int b_k16 = lt & 1;

    for (int i = 0; i < nch; ++i) {
        if (i + 2 < nch) load_chunk(i + 2);
        cp_wait(min(nch - 1 - i, 2));
        __syncthreads();

        const uint32_t s0 = sb + (uint32_t)(i % NSTAGE) * STAGE_B;
        #pragma unroll
        for (int ks = 0; ks < 2; ++ks) {
            uint32_t afh[4][4], bfh[4][4], tf[4][4];
            // A hi frags (m64)
            #pragma unroll
            for (int mi = 0; mi < 4; ++mi)
                ldm_x4(afh[mi], s0 + (wm + mi * 16 + a_row_in) * (PITCH * 2)
                                 + ks * 32 + a_k16 * 16);
            // B hi frags (n64)
            #pragma unroll
            for (int ni = 0; ni < 4; ++ni)
                ldm_x4(bfh[ni], s0 + 2 * TILE_B
                                 + (wn + ni * 16 + b_n_in) * (PITCH * 2)
                                 + ks * 32 + b_k16 * 16);
            // hi*hi
            #pragma unroll
            for (int mi = 0; mi < 4; ++mi)
                #pragma unroll
                for (int nj = 0; nj < 8; ++nj)
                    mma_bf16(acc[mi][nj], afh[mi], bfh[nj >> 1][(nj & 1) * 2],
                             bfh[nj >> 1][(nj & 1) * 2 + 1]);
            // B lo frags -> hi*lo
            #pragma unroll
            for (int ni = 0; ni < 4; ++ni)
                ldm_x4(tf[ni], s0 + 3 * TILE_B
                                + (wn + ni * 16 + b_n_in) * (PITCH * 2)
                                + ks * 32 + b_k16 * 16);
            #pragma unroll
            for (int mi = 0; mi < 4; ++mi)
                #pragma unroll
                for (int nj = 0; nj < 8; ++nj)
                    mma_bf16(acc[mi][nj], afh[mi], tf[nj >> 1][(nj & 1) * 2],
                             tf[nj >> 1][(nj & 1) * 2 + 1]);
            // A lo frags -> lo*hi
            #pragma unroll
            for (int mi = 0; mi < 4; ++mi)
                ldm_x4(tf[mi], s0 + TILE_B + (wm + mi * 16 + a_row_in) * (PITCH * 2)
                                + ks * 32 + a_k16 * 16);
            #pragma unroll
            for (int mi = 0; mi < 4; ++mi)
                #pragma unroll
                for (int nj = 0; nj < 8; ++nj)
                    mma_bf16(acc[mi][nj], tf[mi], bfh[nj >> 1][(nj & 1) * 2],
                             bfh[nj >> 1][(nj & 1) * 2 + 1]);
        }
        __syncthreads();
    }

    const int er = lane >> 2;
    const int ec = (lane & 3) * 2;
    #pragma unroll
    for (int mi = 0; mi < 4; ++mi) {
        #pragma unroll
        for (int nj = 0; nj < 8; ++nj) {
            int col = bn + wn + nj * 8 + ec;
            float b0 = bias[col], b1 = bias[col + 1];
            int r0 = bm + wm + mi * 16 + er;
            float2 v0 = make_float2(acc[mi][nj][0] + b0, acc[mi][nj][1] + b1);
            float2 v1 = make_float2(acc[mi][nj][2] + b0, acc[mi][nj][3] + b1);
            *(float2*)&C[(size_t)r0 * N + col] = v0;
            *(float2*)&C[(size_t)(r0 + 8) * N + col] = v1;
        }
    }
}

// ---------------- attention v2: blocked f32x2, one CTA per (head, window) --
#define QKP 34
__global__ __launch_bounds__(256)
void attn_kernel(const float* __restrict__ mask,
                 const float* __restrict__ logit_scale) {
    const int h = blockIdx.x;
    const int win = blockIdx.y;
    __shared__ float qs[64][QKP];
    __shared__ float ks[64][QKP];
    __shared__ float vs[64][QKP];
    __shared__ float S[64][65];
    const int tid = threadIdx.x;

    const size_t base = (size_t)win * 64 * QKVN + h * HDIM;
    #pragma unroll
    for (int l = 0; l < 2; ++l) {
        int t = tid + l * 256;
        int n = t >> 3;
        int f = (t & 7) << 2;
        const float* rowp = &g_qkv[base + (size_t)n * QKVN];
        float4 qv = *(const float4*)&rowp[f];
        float4 kv = *(const float4*)&rowp[512 + f];
        float4 vv = *(const float4*)&rowp[1024 + f];
        *(float2*)&qs[n][f]     = make_float2(qv.x, qv.y);
        *(float2*)&qs[n][f + 2] = make_float2(qv.z, qv.w);
        *(float2*)&ks[n][f]     = make_float2(kv.x, kv.y);
        *(float2*)&ks[n][f + 2] = make_float2(kv.z, kv.w);
        *(float2*)&vs[n][f]     = make_float2(vv.x, vv.y);
        *(float2*)&vs[n][f + 2] = make_float2(vv.z, vv.w);
    }
    float scale = fexp(fminf(logit_scale[h], LOGMAX));
    __syncthreads();

    {
        int r = tid >> 1;
        int half = tid & 1;
        float* row = (r < 64) ? qs[r] : ks[r - 64];
        float ss = 0.f;
        #pragma unroll
        for (int d2 = 0; d2 < 16; d2 += 2) {
            float2 v = *(float2*)&row[half * 16 + d2];
            ss += v.x * v.x + v.y * v.y;
        }
        ss += __shfl_xor_sync(0xffffffffu, ss, 1);
        float inv = rsqrtf(ss);
        if (r < 64) inv *= scale;
        #pragma unroll
        for (int d = 0; d < 16; ++d) row[half * 16 + d] *= inv;
    }
    __syncthreads();

    const int ty = tid >> 4, tx = tid & 15;
    unsigned long long a2[4][4];
    #pragma unroll
    for (int ii = 0; ii < 4; ++ii)
        #pragma unroll
        for (int jj = 0; jj < 4; ++jj) a2[ii][jj] = 0ull;
    #pragma unroll
    for (int d2 = 0; d2 < 16; ++d2) {
        unsigned long long q2[4], k2[4];
        #pragma unroll
        for (int ii = 0; ii < 4; ++ii)
            q2[ii] = *(unsigned long long*)&qs[4 * ty + ii][2 * d2];
        #pragma unroll
        for (int jj = 0; jj < 4; ++jj)
            k2[jj] = *(unsigned long long*)&ks[tx + 16 * jj][2 * d2];
        #pragma unroll
        for (int ii = 0; ii < 4; ++ii)
            #pragma unroll
            for (int jj = 0; jj < 4; ++jj)
                ffma2(a2[ii][jj], q2[ii], k2[jj]);
    }
    const float* bias_h = &g_bias[h * 4096];
    const float* mask_w = &mask[(size_t)(win & (NWMASK - 1)) * 4096];
    float sv[4][4];
    #pragma unroll
    for (int ii = 0; ii < 4; ++ii) {
        int r = 4 * ty + ii;
        #pragma unroll
        for (int jj = 0; jj < 4; ++jj) {
            int c = tx + 16 * jj;
            float x, y;
            unpack2(a2[ii][jj], x, y);
            sv[ii][jj] = x + y + bias_h[r * 64 + c] + mask_w[r * 64 + c];
        }
    }
    float sr[4];
    #pragma unroll
    for (int ii = 0; ii < 4; ++ii) {
        float m = fmaxf(fmaxf(sv[ii][0], sv[ii][1]), fmaxf(sv[ii][2], sv[ii][3]));
        m = fmaxf(m, __shfl_xor_sync(0xffffffffu, m, 1));
        m = fmaxf(m, __shfl_xor_sync(0xffffffffu, m, 2));
        m = fmaxf(m, __shfl_xor_sync(0xffffffffu, m, 4));
        m = fmaxf(m, __shfl_xor_sync(0xffffffffu, m, 8));
        float s = 0.f;
        #pragma unroll
        for (int jj = 0; jj < 4; ++jj) {
            sv[ii][jj] = fexp(sv[ii][jj] - m);
            s += sv[ii][jj];
        }
        s += __shfl_xor_sync(0xffffffffu, s, 1);
        s += __shfl_xor_sync(0xffffffffu, s, 2);
        s += __shfl_xor_sync(0xffffffffu, s, 4);
        s += __shfl_xor_sync(0xffffffffu, s, 8);
        sr[ii] = __frcp_rn(s);
    }
    #pragma unroll
    for (int ii = 0; ii < 4; ++ii)
        #pragma unroll
        for (int jj = 0; jj < 4; ++jj)
            S[4 * ty + ii][tx + 16 * jj] = sv[ii][jj] * sr[ii];
    __syncthreads();

    const int ti = ty, tu = tx;
    unsigned long long pa[4] = {0ull, 0ull, 0ull, 0ull};
    #pragma unroll 4
    for (int j = 0; j < 64; ++j) {
        unsigned long long v2 = *(unsigned long long*)&vs[j][2 * tu];
        #pragma unroll
        for (int ii = 0; ii < 4; ++ii) {
            float p = S[4 * ti + ii][j];
            ffma2(pa[ii], pack2(p, p), v2);
        }
    }
    #pragma unroll
    for (int ii = 0; ii < 4; ++ii) {
        float x, y;
        unpack2(pa[ii], x, y);
        size_t orow = ((size_t)win * 64 + 4 * ti + ii) * CHANS + h * HDIM + 2 * tu;
        __nv_bfloat16 hx, lx, hy, ly;
        split1(x, hx, lx);
        split1(y, hy, ly);
        __nv_bfloat162 hv, lv;
        hv.x = hx; hv.y = hy;
        lv.x = lx; lv.y = ly;
        *(__nv_bfloat162*)&g_ao_hi[orow] = hv;
        *(__nv_bfloat162*)&g_ao_lo[orow] = lv;
    }
}

// ---------------- launch ----------------
extern "C" void kernel_launch(void* const* d_in, const int* in_sizes, int n_in,
                              void* d_out, int out_size) {
    const float* x       = (const float*)d_in[0];
    const float* mask    = (const float*)d_in[1];
    const float* rel_t   = (const float*)d_in[2];
    const float* w_qkv   = (const float*)d_in[3];
    const float* q_bias  = (const float*)d_in[4];
    const float* v_bias  = (const float*)d_in[5];
    const float* lscale  = (const float*)d_in[6];
    const float* cpb_w1  = (const float*)d_in[7];
    const float* cpb_b1  = (const float*)d_in[8];
    const float* cpb_w2  = (const float*)d_in[9];
    const float* proj_w  = (const float*)d_in[10];
    const float* proj_b  = (const float*)d_in[11];
    float* out = (float*)d_out;

    void *p_qkv, *p_qb, *p_xh, *p_xl, *p_aoh, *p_aol, *p_wqh, *p_wql, *p_wph, *p_wpl;
    cudaGetSymbolAddress(&p_qkv, g_qkv);
    cudaGetSymbolAddress(&p_qb, g_qkv_bias);
    cudaGetSymbolAddress(&p_xh, g_x_hi);
    cudaGetSymbolAddress(&p_xl, g_x_lo);
    cudaGetSymbolAddress(&p_aoh, g_ao_hi);
    cudaGetSymbolAddress(&p_aol, g_ao_lo);
    cudaGetSymbolAddress(&p_wqh, g_wq_hi);
    cudaGetSymbolAddress(&p_wql, g_wq_lo);
    cudaGetSymbolAddress(&p_wph, g_wp_hi);
    cudaGetSymbolAddress(&p_wpl, g_wp_lo);

    cudaFuncSetAttribute(hmma_gemm, cudaFuncAttributeMaxDynamicSharedMemorySize, GEMM_SMEM);

    qkvbias_kernel<<<6, 256>>>(q_bias, v_bias);
    cpb_table_kernel<<<225, 512>>>(rel_t, cpb_w1, cpb_b1, cpb_w2);
    bias_expand_kernel<<<256, 256>>>();

    split_x_kernel<<<(MROWS * CHANS) / 1024, 256>>>(x);
    wsplit_kernel<<<(CHANS * QKVN + 255) / 256, 256>>>(
        w_qkv, (__nv_bfloat16*)p_wqh, (__nv_bfloat16*)p_wql, CHANS, QKVN);
    wsplit_kernel<<<(CHANS * CHANS + 255) / 256, 256>>>(
        proj_w, (__nv_bfloat16*)p_wph, (__nv_bfloat16*)p_wpl, CHANS, CHANS);

    hmma_gemm<<<dim3(QKVN / 128, MROWS / 128), 128, GEMM_SMEM>>>(
        (const __nv_bfloat16*)p_xh, (const __nv_bfloat16*)p_xl,
        (const __nv_bfloat16*)p_wqh, (const __nv_bfloat16*)p_wql,
        (const float*)p_qb, (float*)p_qkv, MROWS, QKVN, CHANS);

    attn_kernel<<<dim3(NHEAD, BWIN), 256>>>(mask, lscale);

    hmma_gemm<<<dim3(CHANS / 128, MROWS / 128), 128, GEMM_SMEM>>>(
        (const __nv_bfloat16*)p_aoh, (const __nv_bfloat16*)p_aol,
        (const __nv_bfloat16*)p_wph, (const __nv_bfloat16*)p_wpl,
        proj_b, out, MROWS, CHANS, CHANS);
}

// round 7
// speedup vs baseline: 1.0583x; 1.0583x over previous
#include <cuda_runtime.h>
#include <cuda_bf16.h>
#include <math.h>
#include <stdint.h>

// ---------------- problem constants ----------------
#define BWIN   2048
#define NTOK   64
#define CHANS  512
#define NHEAD  16
#define HDIM   32
#define NWMASK 256
#define MROWS  (BWIN * NTOK)     // 131072
#define QKVN   (3 * CHANS)       // 1536
#define LOGMAX 4.6051701859880914f

// ---------------- scratch ----------------
__device__ float g_qkv[(size_t)MROWS * QKVN];
__device__ __nv_bfloat16 g_x_hi[(size_t)MROWS * CHANS];
__device__ __nv_bfloat16 g_x_lo[(size_t)MROWS * CHANS];
__device__ __nv_bfloat16 g_ao_hi[(size_t)MROWS * CHANS];
__device__ __nv_bfloat16 g_ao_lo[(size_t)MROWS * CHANS];
__device__ __nv_bfloat16 g_wq_hi[(size_t)QKVN * CHANS];   // [N,K] transposed
__device__ __nv_bfloat16 g_wq_lo[(size_t)QKVN * CHANS];
__device__ __nv_bfloat16 g_wp_hi[(size_t)CHANS * CHANS];
__device__ __nv_bfloat16 g_wp_lo[(size_t)CHANS * CHANS];
__device__ float g_table[225 * NHEAD];
__device__ float g_bias[NHEAD * NTOK * NTOK];
__device__ float g_qkv_bias[QKVN];

// ---------------- helpers ----------------
__device__ __forceinline__ uint32_t smem_u32(const void* p) {
    uint32_t a;
    asm("{ .reg .u64 t; cvta.to.shared.u64 t, %1; cvt.u32.u64 %0, t; }" : "=r"(a) : "l"(p));
    return a;
}
__device__ __forceinline__ void cp16(uint32_t dst, const void* src) {
    asm volatile("cp.async.cg.shared.global [%0], [%1], 16;" :: "r"(dst), "l"(src));
}
#define CP_COMMIT() asm volatile("cp.async.commit_group;" ::: "memory")
__device__ __forceinline__ void cp_wait(int rem) {
    if (rem >= 1) asm volatile("cp.async.wait_group 1;" ::: "memory");
    else          asm volatile("cp.async.wait_group 0;" ::: "memory");
}
__device__ __forceinline__ void ldm_x4(uint32_t* r, uint32_t addr) {
    asm volatile("ldmatrix.sync.aligned.m8n8.x4.shared.b16 {%0,%1,%2,%3}, [%4];"
                 : "=r"(r[0]), "=r"(r[1]), "=r"(r[2]), "=r"(r[3]) : "r"(addr));
}
__device__ __forceinline__ void mma_bf16(float* d, const uint32_t* a, uint32_t b0, uint32_t b1) {
    asm volatile(
        "mma.sync.aligned.m16n8k16.row.col.f32.bf16.bf16.f32 "
        "{%0,%1,%2,%3}, {%4,%5,%6,%7}, {%8,%9}, {%0,%1,%2,%3};"
        : "+f"(d[0]), "+f"(d[1]), "+f"(d[2]), "+f"(d[3])
        : "r"(a[0]), "r"(a[1]), "r"(a[2]), "r"(a[3]), "r"(b0), "r"(b1));
}
__device__ __forceinline__ void split1(float x, __nv_bfloat16& h, __nv_bfloat16& l) {
    h = __float2bfloat16(x);
    l = __float2bfloat16(x - __bfloat162float(h));
}
// packed f32x2 FMA (Blackwell FFMA2, PTX-only)
__device__ __forceinline__ void ffma2(unsigned long long& d,
                                      unsigned long long a, unsigned long long b) {
    asm("fma.rn.f32x2 %0, %1, %2, %0;" : "+l"(d) : "l"(a), "l"(b));
}
__device__ __forceinline__ unsigned long long pack2(float x, float y) {
    unsigned long long r;
    asm("mov.b64 %0, {%1, %2};" : "=l"(r) : "f"(x), "f"(y));
    return r;
}
__device__ __forceinline__ void unpack2(unsigned long long v, float& x, float& y) {
    asm("mov.b64 {%0, %1}, %2;" : "=f"(x), "=f"(y) : "l"(v));
}
// fast exp via FMA polynomial (no MUFU)
__device__ __forceinline__ float fexp(float x) {
    float t = fmaxf(x * 1.442695040888963f, -125.f);
    float n = rintf(t);
    float f = t - n;
    float p = 1.3392138e-3f;
    p = fmaf(p, f, 9.6181291e-3f);
    p = fmaf(p, f, 5.5504108e-2f);
    p = fmaf(p, f, 2.4022650e-1f);
    p = fmaf(p, f, 6.9314718e-1f);
    p = fmaf(p, f, 1.0f);
    return __int_as_float(((int)n + 127) << 23) * p;
}

// ---------------- tiny prep kernels ----------------
__global__ void qkvbias_kernel(const float* __restrict__ qb,
                               const float* __restrict__ vb) {
    int n = blockIdx.x * 256 + threadIdx.x;
    if (n >= QKVN) return;
    float v = 0.f;
    if (n < CHANS) v = qb[n];
    else if (n >= 2 * CHANS) v = vb[n - 2 * CHANS];
    g_qkv_bias[n] = v;
}

__global__ void cpb_table_kernel(const float* __restrict__ rel_table,
                                 const float* __restrict__ w1,
                                 const float* __restrict__ b1,
                                 const float* __restrict__ w2) {
    int p = blockIdx.x;
    int j = threadIdx.x;
    __shared__ float hid[512];
    float t0 = rel_table[p * 2 + 0];
    float t1 = rel_table[p * 2 + 1];
    hid[j] = fmaxf(t0 * w1[j] + t1 * w1[512 + j] + b1[j], 0.f);
    __syncthreads();
    if (j < NHEAD) {
        float acc = 0.f;
        #pragma unroll 8
        for (int r = 0; r < 512; ++r) acc += hid[r] * w2[r * NHEAD + j];
        g_table[p * NHEAD + j] = acc;
    }
}

__global__ void bias_expand_kernel() {
    int id = blockIdx.x * 256 + threadIdx.x;
    int h = id >> 12;
    int i = (id >> 6) & 63;
    int j = id & 63;
    int idx = ((i >> 3) - (j >> 3) + 7) * 15 + ((i & 7) - (j & 7) + 7);
    float b = g_table[idx * NHEAD + h];
    g_bias[id] = 16.f / (1.f + fexp(-b));
}

__global__ void split_x_kernel(const float* __restrict__ src) {
    size_t i = ((size_t)blockIdx.x * 256 + threadIdx.x) * 4;
    float4 v = *(const float4*)&src[i];
    __align__(8) __nv_bfloat16 h[4], l[4];
    split1(v.x, h[0], l[0]);
    split1(v.y, h[1], l[1]);
    split1(v.z, h[2], l[2]);
    split1(v.w, h[3], l[3]);
    *(uint2*)&g_x_hi[i] = *(uint2*)h;
    *(uint2*)&g_x_lo[i] = *(uint2*)l;
}

__global__ void wsplit_kernel(const float* __restrict__ w,
                              __nv_bfloat16* __restrict__ hiT,
                              __nv_bfloat16* __restrict__ loT,
                              int K, int N) {
    int idx = blockIdx.x * 256 + threadIdx.x;
    if (idx >= K * N) return;
    int k = idx / N, n = idx % N;
    __nv_bfloat16 h, l;
    split1(w[idx], h, l);
    hiT[(size_t)n * K + k] = h;
    loT[(size_t)n * K + k] = l;
}

// ---------------- HMMA bf16x3 GEMM ----------------
// C[M,N] = (Ahi+Alo)[M,K] @ (Bhi+Blo)[N,K]^T + bias[N]
// BM=256 BN=128 BK=32, 256 thr / 8 warps (4Mx2N), warp tile 64x64,
// 2-stage cp.async pipeline (120KB smem, 1 CTA/SM, 2 warps/SMSP).
#define PITCH 40
#define A_TILE_B (256 * PITCH * 2)       // 20480 B
#define B_TILE_B (128 * PITCH * 2)       // 10240 B
#define STAGE_B (2 * A_TILE_B + 2 * B_TILE_B)   // 61440 B
#define NSTAGE 2
#define GEMM_SMEM (NSTAGE * STAGE_B)     // 122880 B

__global__ void __launch_bounds__(256, 1)
hmma_gemm(const __nv_bfloat16* __restrict__ Ahi, const __nv_bfloat16* __restrict__ Alo,
          const __nv_bfloat16* __restrict__ Bhi, const __nv_bfloat16* __restrict__ Blo,
          const float* __restrict__ bias, float* __restrict__ C,
          int M, int N, int K) {
    extern __shared__ char smem[];
    const uint32_t sb = smem_u32(smem);
    const int tid = threadIdx.x;
    const int wid = tid >> 5, lane = tid & 31;
    const int bm = blockIdx.y * 256;
    const int bn = blockIdx.x * 128;
    const int wm = (wid >> 1) * 64;      // 4 M-warps
    const int wn = (wid & 1) * 64;       // 2 N-warps
    const int nch = K >> 5;

    // A loader: 256 rows x 32 cols
    auto load_a = [&](const __nv_bfloat16* g, int k0, uint32_t off) {
        #pragma unroll
        for (int c = tid; c < 1024; c += 256) {
            int row = c >> 2, chunk = c & 3;
            cp16(sb + off + row * (PITCH * 2) + chunk * 16,
                 g + (size_t)(bm + row) * K + k0 + chunk * 8);
        }
    };
    // B loader: 128 rows x 32 cols
    auto load_b = [&](const __nv_bfloat16* g, int k0, uint32_t off) {
        #pragma unroll
        for (int c = tid; c < 512; c += 256) {
            int row = c >> 2, chunk = c & 3;
            cp16(sb + off + row * (PITCH * 2) + chunk * 16,
                 g + (size_t)(bn + row) * K + k0 + chunk * 8);
        }
    };
    auto load_chunk = [&](int chunk) {
        int k0 = chunk << 5;
        uint32_t s0 = (uint32_t)(chunk & 1) * STAGE_B;
        load_a(Ahi, k0, s0);
        load_a(Alo, k0, s0 + A_TILE_B);
        load_b(Bhi, k0, s0 + 2 * A_TILE_B);
        load_b(Blo, k0, s0 + 2 * A_TILE_B + B_TILE_B);
        CP_COMMIT();
    };

    float acc[4][8][4] = {};   // warp tile 64x64

    load_chunk(0);

    const int lt = lane >> 3;
    const int lr = lane & 7;
    const int a_row_in = ((lt & 1) << 3) + lr;
    const int a_k16 = lt >> 1;
    const int b_n_in = ((lt >> 1) << 3) + lr;
    const int b_k16 = lt & 1;

    for (int i = 0; i < nch; ++i) {
        if (i + 1 < nch) load_chunk(i + 1);
        cp_wait(i + 1 < nch ? 1 : 0);
        __syncthreads();

        const uint32_t s0 = sb + (uint32_t)(i & 1) * STAGE_B;
        #pragma unroll
        for (int ks = 0; ks < 2; ++ks) {
            uint32_t afh[4][4], bfh[4][4], tf[4][4];
            // A hi frags (m64)
            #pragma unroll
            for (int mi = 0; mi < 4; ++mi)
                ldm_x4(afh[mi], s0 + (wm + mi * 16 + a_row_in) * (PITCH * 2)
                                 + ks * 32 + a_k16 * 16);
            // B hi frags (n64)
            #pragma unroll
            for (int ni = 0; ni < 4; ++ni)
                ldm_x4(bfh[ni], s0 + 2 * A_TILE_B
                                 + (wn + ni * 16 + b_n_in) * (PITCH * 2)
                                 + ks * 32 + b_k16 * 16);
            // hi*hi
            #pragma unroll
            for (int mi = 0; mi < 4; ++mi)
                #pragma unroll
                for (int nj = 0; nj < 8; ++nj)
                    mma_bf16(acc[mi][nj], afh[mi], bfh[nj >> 1][(nj & 1) * 2],
                             bfh[nj >> 1][(nj & 1) * 2 + 1]);
            // B lo frags -> hi*lo
            #pragma unroll
            for (int ni = 0; ni < 4; ++ni)
                ldm_x4(tf[ni], s0 + 2 * A_TILE_B + B_TILE_B
                                + (wn + ni * 16 + b_n_in) * (PITCH * 2)
                                + ks * 32 + b_k16 * 16);
            #pragma unroll
            for (int mi = 0; mi < 4; ++mi)
                #pragma unroll
                for (int nj = 0; nj < 8; ++nj)
                    mma_bf16(acc[mi][nj], afh[mi], tf[nj >> 1][(nj & 1) * 2],
                             tf[nj >> 1][(nj & 1) * 2 + 1]);
            // A lo frags -> lo*hi
            #pragma unroll
            for (int mi = 0; mi < 4; ++mi)
                ldm_x4(tf[mi], s0 + A_TILE_B + (wm + mi * 16 + a_row_in) * (PITCH * 2)
                                + ks * 32 + a_k16 * 16);
            #pragma unroll
            for (int mi = 0; mi < 4; ++mi)
                #pragma unroll
                for (int nj = 0; nj < 8; ++nj)
                    mma_bf16(acc[mi][nj], tf[mi], bfh[nj >> 1][(nj & 1) * 2],
                             bfh[nj >> 1][(nj & 1) * 2 + 1]);
        }
        __syncthreads();
    }

    const int er = lane >> 2;
    const int ec = (lane & 3) * 2;
    #pragma unroll
    for (int mi = 0; mi < 4; ++mi) {
        #pragma unroll
        for (int nj = 0; nj < 8; ++nj) {
            int col = bn + wn + nj * 8 + ec;
            float b0 = bias[col], b1 = bias[col + 1];
            int r0 = bm + wm + mi * 16 + er;
            float2 v0 = make_float2(acc[mi][nj][0] + b0, acc[mi][nj][1] + b1);
            float2 v1 = make_float2(acc[mi][nj][2] + b0, acc[mi][nj][3] + b1);
            *(float2*)&C[(size_t)r0 * N + col] = v0;
            *(float2*)&C[(size_t)(r0 + 8) * N + col] = v1;
        }
    }
}

// ---------------- attention v2: blocked f32x2, one CTA per (head, window) --
#define QKP 34
__global__ __launch_bounds__(256)
void attn_kernel(const float* __restrict__ mask,
                 const float* __restrict__ logit_scale) {
    const int h = blockIdx.x;
    const int win = blockIdx.y;
    __shared__ float qs[64][QKP];
    __shared__ float ks[64][QKP];
    __shared__ float vs[64][QKP];
    __shared__ float S[64][65];
    const int tid = threadIdx.x;

    const size_t base = (size_t)win * 64 * QKVN + h * HDIM;
    #pragma unroll
    for (int l = 0; l < 2; ++l) {
        int t = tid + l * 256;
        int n = t >> 3;
        int f = (t & 7) << 2;
        const float* rowp = &g_qkv[base + (size_t)n * QKVN];
        float4 qv = *(const float4*)&rowp[f];
        float4 kv = *(const float4*)&rowp[512 + f];
        float4 vv = *(const float4*)&rowp[1024 + f];
        *(float2*)&qs[n][f]     = make_float2(qv.x, qv.y);
        *(float2*)&qs[n][f + 2] = make_float2(qv.z, qv.w);
        *(float2*)&ks[n][f]     = make_float2(kv.x, kv.y);
        *(float2*)&ks[n][f + 2] = make_float2(kv.z, kv.w);
        *(float2*)&vs[n][f]     = make_float2(vv.x, vv.y);
        *(float2*)&vs[n][f + 2] = make_float2(vv.z, vv.w);
    }
    float scale = fexp(fminf(logit_scale[h], LOGMAX));
    __syncthreads();

    {
        int r = tid >> 1;
        int half = tid & 1;
        float* row = (r < 64) ? qs[r] : ks[r - 64];
        float ss = 0.f;
        #pragma unroll
        for (int d2 = 0; d2 < 16; d2 += 2) {
            float2 v = *(float2*)&row[half * 16 + d2];
            ss += v.x * v.x + v.y * v.y;
        }
        ss += __shfl_xor_sync(0xffffffffu, ss, 1);
        float inv = rsqrtf(ss);
        if (r < 64) inv *= scale;
        #pragma unroll
        for (int d = 0; d < 16; ++d) row[half * 16 + d] *= inv;
    }
    __syncthreads();

    const int ty = tid >> 4, tx = tid & 15;
    unsigned long long a2[4][4];
    #pragma unroll
    for (int ii = 0; ii < 4; ++ii)
        #pragma unroll
        for (int jj = 0; jj < 4; ++jj) a2[ii][jj] = 0ull;
    #pragma unroll
    for (int d2 = 0; d2 < 16; ++d2) {
        unsigned long long q2[4], k2[4];
        #pragma unroll
        for (int ii = 0; ii < 4; ++ii)
            q2[ii] = *(unsigned long long*)&qs[4 * ty + ii][2 * d2];
        #pragma unroll
        for (int jj = 0; jj < 4; ++jj)
            k2[jj] = *(unsigned long long*)&ks[tx + 16 * jj][2 * d2];
        #pragma unroll
        for (int ii = 0; ii < 4; ++ii)
            #pragma unroll
            for (int jj = 0; jj < 4; ++jj)
                ffma2(a2[ii][jj], q2[ii], k2[jj]);
    }
    const float* bias_h = &g_bias[h * 4096];
    const float* mask_w = &mask[(size_t)(win & (NWMASK - 1)) * 4096];
    float sv[4][4];
    #pragma unroll
    for (int ii = 0; ii < 4; ++ii) {
        int r = 4 * ty + ii;
        #pragma unroll
        for (int jj = 0; jj < 4; ++jj) {
            int c = tx + 16 * jj;
            float x, y;
            unpack2(a2[ii][jj], x, y);
            sv[ii][jj] = x + y + bias_h[r * 64 + c] + mask_w[r * 64 + c];
        }
    }
    float sr[4];
    #pragma unroll
    for (int ii = 0; ii < 4; ++ii) {
        float m = fmaxf(fmaxf(sv[ii][0], sv[ii][1]), fmaxf(sv[ii][2], sv[ii][3]));
        m = fmaxf(m, __shfl_xor_sync(0xffffffffu, m, 1));
        m = fmaxf(m, __shfl_xor_sync(0xffffffffu, m, 2));
        m = fmaxf(m, __shfl_xor_sync(0xffffffffu, m, 4));
        m = fmaxf(m, __shfl_xor_sync(0xffffffffu, m, 8));
        float s = 0.f;
        #pragma unroll
        for (int jj = 0; jj < 4; ++jj) {
            sv[ii][jj] = fexp(sv[ii][jj] - m);
            s += sv[ii][jj];
        }
        s += __shfl_xor_sync(0xffffffffu, s, 1);
        s += __shfl_xor_sync(0xffffffffu, s, 2);
        s += __shfl_xor_sync(0xffffffffu, s, 4);
        s += __shfl_xor_sync(0xffffffffu, s, 8);
        sr[ii] = __frcp_rn(s);
    }
    #pragma unroll
    for (int ii = 0; ii < 4; ++ii)
        #pragma unroll
        for (int jj = 0; jj < 4; ++jj)
            S[4 * ty + ii][tx + 16 * jj] = sv[ii][jj] * sr[ii];
    __syncthreads();

    const int ti = ty, tu = tx;
    unsigned long long pa[4] = {0ull, 0ull, 0ull, 0ull};
    #pragma unroll 4
    for (int j = 0; j < 64; ++j) {
        unsigned long long v2 = *(unsigned long long*)&vs[j][2 * tu];
        #pragma unroll
        for (int ii = 0; ii < 4; ++ii) {
            float p = S[4 * ti + ii][j];
            ffma2(pa[ii], pack2(p, p), v2);
        }
    }
    #pragma unroll
    for (int ii = 0; ii < 4; ++ii) {
        float x, y;
        unpack2(pa[ii], x, y);
        size_t orow = ((size_t)win * 64 + 4 * ti + ii) * CHANS + h * HDIM + 2 * tu;
        __nv_bfloat16 hx, lx, hy, ly;
        split1(x, hx, lx);
        split1(y, hy, ly);
        __nv_bfloat162 hv, lv;
        hv.x = hx; hv.y = hy;
        lv.x = lx; lv.y = ly;
        *(__nv_bfloat162*)&g_ao_hi[orow] = hv;
        *(__nv_bfloat162*)&g_ao_lo[orow] = lv;
    }
}

// ---------------- launch ----------------
extern "C" void kernel_launch(void* const* d_in, const int* in_sizes, int n_in,
                              void* d_out, int out_size) {
    const float* x       = (const float*)d_in[0];
    const float* mask    = (const float*)d_in[1];
    const float* rel_t   = (const float*)d_in[2];
    const float* w_qkv   = (const float*)d_in[3];
    const float* q_bias  = (const float*)d_in[4];
    const float* v_bias  = (const float*)d_in[5];
    const float* lscale  = (const float*)d_in[6];
    const float* cpb_w1  = (const float*)d_in[7];
    const float* cpb_b1  = (const float*)d_in[8];
    const float* cpb_w2  = (const float*)d_in[9];
    const float* proj_w  = (const float*)d_in[10];
    const float* proj_b  = (const float*)d_in[11];
    float* out = (float*)d_out;

    void *p_qkv, *p_qb, *p_xh, *p_xl, *p_aoh, *p_aol, *p_wqh, *p_wql, *p_wph, *p_wpl;
    cudaGetSymbolAddress(&p_qkv, g_qkv);
    cudaGetSymbolAddress(&p_qb, g_qkv_bias);
    cudaGetSymbolAddress(&p_xh, g_x_hi);
    cudaGetSymbolAddress(&p_xl, g_x_lo);
    cudaGetSymbolAddress(&p_aoh, g_ao_hi);
    cudaGetSymbolAddress(&p_aol, g_ao_lo);
    cudaGetSymbolAddress(&p_wqh, g_wq_hi);
    cudaGetSymbolAddress(&p_wql, g_wq_lo);
    cudaGetSymbolAddress(&p_wph, g_wp_hi);
    cudaGetSymbolAddress(&p_wpl, g_wp_lo);

    cudaFuncSetAttribute(hmma_gemm, cudaFuncAttributeMaxDynamicSharedMemorySize, GEMM_SMEM);

    qkvbias_kernel<<<6, 256>>>(q_bias, v_bias);
    cpb_table_kernel<<<225, 512>>>(rel_t, cpb_w1, cpb_b1, cpb_w2);
    bias_expand_kernel<<<256, 256>>>();

    split_x_kernel<<<(MROWS * CHANS) / 1024, 256>>>(x);
    wsplit_kernel<<<(CHANS * QKVN + 255) / 256, 256>>>(
        w_qkv, (__nv_bfloat16*)p_wqh, (__nv_bfloat16*)p_wql, CHANS, QKVN);
    wsplit_kernel<<<(CHANS * CHANS + 255) / 256, 256>>>(
        proj_w, (__nv_bfloat16*)p_wph, (__nv_bfloat16*)p_wpl, CHANS, CHANS);

    // QKV: [131072,512] @ [512,1536]
    hmma_gemm<<<dim3(QKVN / 128, MROWS / 256), 256, GEMM_SMEM>>>(
        (const __nv_bfloat16*)p_xh, (const __nv_bfloat16*)p_xl,
        (const __nv_bfloat16*)p_wqh, (const __nv_bfloat16*)p_wql,
        (const float*)p_qb, (float*)p_qkv, MROWS, QKVN, CHANS);

    attn_kernel<<<dim3(NHEAD, BWIN), 256>>>(mask, lscale);

    // proj: [131072,512] @ [512,512]
    hmma_gemm<<<dim3(CHANS / 128, MROWS / 256), 256, GEMM_SMEM>>>(
        (const __nv_bfloat16*)p_aoh, (const __nv_bfloat16*)p_aol,
        (const __nv_bfloat16*)p_wph, (const __nv_bfloat16*)p_wpl,
        proj_b, out, MROWS, CHANS, CHANS);
}

// round 8
// speedup vs baseline: 1.1906x; 1.1250x over previous
#include <cuda_runtime.h>
#include <cuda_bf16.h>
#include <math.h>
#include <stdint.h>

// ---------------- problem constants ----------------
#define BWIN   2048
#define NTOK   64
#define CHANS  512
#define NHEAD  16
#define HDIM   32
#define NWMASK 256
#define MROWS  (BWIN * NTOK)     // 131072
#define QKVN   (3 * CHANS)       // 1536
#define LOGMAX 4.6051701859880914f

// ---------------- scratch ----------------
__device__ float g_qkv[(size_t)MROWS * QKVN];
__device__ __nv_bfloat16 g_x_hi[(size_t)MROWS * CHANS];
__device__ __nv_bfloat16 g_x_lo[(size_t)MROWS * CHANS];
__device__ __nv_bfloat16 g_ao_hi[(size_t)MROWS * CHANS];
__device__ __nv_bfloat16 g_ao_lo[(size_t)MROWS * CHANS];
__device__ __nv_bfloat16 g_wq_hi[(size_t)QKVN * CHANS];   // [N,K] transposed
__device__ __nv_bfloat16 g_wq_lo[(size_t)QKVN * CHANS];
__device__ __nv_bfloat16 g_wp_hi[(size_t)CHANS * CHANS];
__device__ __nv_bfloat16 g_wp_lo[(size_t)CHANS * CHANS];
__device__ float g_table[225 * NHEAD];
__device__ float g_bias[NHEAD * NTOK * NTOK];
__device__ float g_qkv_bias[QKVN];

// ---------------- helpers ----------------
__device__ __forceinline__ uint32_t smem_u32(const void* p) {
    uint32_t a;
    asm("{ .reg .u64 t; cvta.to.shared.u64 t, %1; cvt.u32.u64 %0, t; }" : "=r"(a) : "l"(p));
    return a;
}
__device__ __forceinline__ void cp16(uint32_t dst, const void* src) {
    asm volatile("cp.async.cg.shared.global [%0], [%1], 16;" :: "r"(dst), "l"(src));
}
#define CP_COMMIT() asm volatile("cp.async.commit_group;" ::: "memory")
__device__ __forceinline__ void cp_wait(int rem) {
    if (rem >= 2)      asm volatile("cp.async.wait_group 2;" ::: "memory");
    else if (rem == 1) asm volatile("cp.async.wait_group 1;" ::: "memory");
    else               asm volatile("cp.async.wait_group 0;" ::: "memory");
}
__device__ __forceinline__ void ldm_x4(uint32_t* r, uint32_t addr) {
    asm volatile("ldmatrix.sync.aligned.m8n8.x4.shared.b16 {%0,%1,%2,%3}, [%4];"
                 : "=r"(r[0]), "=r"(r[1]), "=r"(r[2]), "=r"(r[3]) : "r"(addr));
}
__device__ __forceinline__ void mma_bf16(float* d, const uint32_t* a, uint32_t b0, uint32_t b1) {
    asm volatile(
        "mma.sync.aligned.m16n8k16.row.col.f32.bf16.bf16.f32 "
        "{%0,%1,%2,%3}, {%4,%5,%6,%7}, {%8,%9}, {%0,%1,%2,%3};"
        : "+f"(d[0]), "+f"(d[1]), "+f"(d[2]), "+f"(d[3])
        : "r"(a[0]), "r"(a[1]), "r"(a[2]), "r"(a[3]), "r"(b0), "r"(b1));
}
__device__ __forceinline__ void split1(float x, __nv_bfloat16& h, __nv_bfloat16& l) {
    h = __float2bfloat16(x);
    l = __float2bfloat16(x - __bfloat162float(h));
}
// packed f32x2 FMA (Blackwell FFMA2, PTX-only)
__device__ __forceinline__ void ffma2(unsigned long long& d,
                                      unsigned long long a, unsigned long long b) {
    asm("fma.rn.f32x2 %0, %1, %2, %0;" : "+l"(d) : "l"(a), "l"(b));
}
__device__ __forceinline__ unsigned long long pack2(float x, float y) {
    unsigned long long r;
    asm("mov.b64 %0, {%1, %2};" : "=l"(r) : "f"(x), "f"(y));
    return r;
}
__device__ __forceinline__ void unpack2(unsigned long long v, float& x, float& y) {
    asm("mov.b64 {%0, %1}, %2;" : "=f"(x), "=f"(y) : "l"(v));
}
// fast exp via FMA polynomial (no MUFU)
__device__ __forceinline__ float fexp(float x) {
    float t = fmaxf(x * 1.442695040888963f, -125.f);
    float n = rintf(t);
    float f = t - n;
    float p = 1.3392138e-3f;
    p = fmaf(p, f, 9.6181291e-3f);
    p = fmaf(p, f, 5.5504108e-2f);
    p = fmaf(p, f, 2.4022650e-1f);
    p = fmaf(p, f, 6.9314718e-1f);
    p = fmaf(p, f, 1.0f);
    return __int_as_float(((int)n + 127) << 23) * p;
}

// ---------------- tiny prep kernels ----------------
__global__ void qkvbias_kernel(const float* __restrict__ qb,
                               const float* __restrict__ vb) {
    int n = blockIdx.x * 256 + threadIdx.x;
    if (n >= QKVN) return;
    float v = 0.f;
    if (n < CHANS) v = qb[n];
    else if (n >= 2 * CHANS) v = vb[n - 2 * CHANS];
    g_qkv_bias[n] = v;
}

__global__ void cpb_table_kernel(const float* __restrict__ rel_table,
                                 const float* __restrict__ w1,
                                 const float* __restrict__ b1,
                                 const float* __restrict__ w2) {
    int p = blockIdx.x;
    int j = threadIdx.x;
    __shared__ float hid[512];
    float t0 = rel_table[p * 2 + 0];
    float t1 = rel_table[p * 2 + 1];
    hid[j] = fmaxf(t0 * w1[j] + t1 * w1[512 + j] + b1[j], 0.f);
    __syncthreads();
    if (j < NHEAD) {
        float acc = 0.f;
        #pragma unroll 8
        for (int r = 0; r < 512; ++r) acc += hid[r] * w2[r * NHEAD + j];
        g_table[p * NHEAD + j] = acc;
    }
}

__global__ void bias_expand_kernel() {
    int id = blockIdx.x * 256 + threadIdx.x;
    int h = id >> 12;
    int i = (id >> 6) & 63;
    int j = id & 63;
    int idx = ((i >> 3) - (j >> 3) + 7) * 15 + ((i & 7) - (j & 7) + 7);
    float b = g_table[idx * NHEAD + h];
    g_bias[id] = 16.f / (1.f + fexp(-b));
}

__global__ void split_x_kernel(const float* __restrict__ src) {
    size_t i = ((size_t)blockIdx.x * 256 + threadIdx.x) * 4;
    float4 v = *(const float4*)&src[i];
    __align__(8) __nv_bfloat16 h[4], l[4];
    split1(v.x, h[0], l[0]);
    split1(v.y, h[1], l[1]);
    split1(v.z, h[2], l[2]);
    split1(v.w, h[3], l[3]);
    *(uint2*)&g_x_hi[i] = *(uint2*)h;
    *(uint2*)&g_x_lo[i] = *(uint2*)l;
}

__global__ void wsplit_kernel(const float* __restrict__ w,
                              __nv_bfloat16* __restrict__ hiT,
                              __nv_bfloat16* __restrict__ loT,
                              int K, int N) {
    int idx = blockIdx.x * 256 + threadIdx.x;
    if (idx >= K * N) return;
    int k = idx / N, n = idx % N;
    __nv_bfloat16 h, l;
    split1(w[idx], h, l);
    hiT[(size_t)n * K + k] = h;
    loT[(size_t)n * K + k] = l;
}

// ---------------- HMMA bf16x3 GEMM ----------------
// C[M,N] = (Ahi+Alo)[M,K] @ (Bhi+Blo)[N,K]^T + bias[N]
// BM=128 BN=128 BK=32, 256 thr / 8 warps (2Mx4N), warp tile 64x32,
// XOR-swizzled 64B rows (no padding), 3-stage cp.async, 96KB smem, 2 CTAs/SM.
#define TILE_B 8192                      // 128 rows x 64 B
#define STAGE_B (4 * TILE_B)             // 32768 B
#define NSTAGE 3
#define GEMM_SMEM (NSTAGE * STAGE_B)     // 98304 B

// swizzled address of (row, 16B-chunk) within a tile
__device__ __forceinline__ uint32_t swz(uint32_t tile, int row, int chunk) {
    return tile + row * 64 + (((chunk + (row >> 1)) & 3) << 4);
}

__global__ void __launch_bounds__(256, 2)
hmma_gemm(const __nv_bfloat16* __restrict__ Ahi, const __nv_bfloat16* __restrict__ Alo,
          const __nv_bfloat16* __restrict__ Bhi, const __nv_bfloat16* __restrict__ Blo,
          const float* __restrict__ bias, float* __restrict__ C,
          int M, int N, int K) {
    extern __shared__ char smem[];
    const uint32_t sb = smem_u32(smem);
    const int tid = threadIdx.x;
    const int wid = tid >> 5, lane = tid & 31;
    const int bm = blockIdx.y * 128;
    const int bn = blockIdx.x * 128;
    const int wm = (wid >> 2) * 64;
    const int wn = (wid & 3) * 32;
    const int nch = K >> 5;

    auto load_tile = [&](const __nv_bfloat16* g, int rowbase, int k0, uint32_t off) {
        #pragma unroll
        for (int c = tid; c < 512; c += 256) {
            int row = c >> 2, chunk = c & 3;
            cp16(swz(sb + off, row, chunk),
                 g + (size_t)(rowbase + row) * K + k0 + chunk * 8);
        }
    };
    auto load_chunk = [&](int chunk) {
        int k0 = chunk << 5;
        uint32_t s0 = (uint32_t)(chunk % NSTAGE) * STAGE_B;
        load_tile(Ahi, bm, k0, s0);
        load_tile(Alo, bm, k0, s0 + TILE_B);
        load_tile(Bhi, bn, k0, s0 + 2 * TILE_B);
        load_tile(Blo, bn, k0, s0 + 3 * TILE_B);
        CP_COMMIT();
    };

    float acc[4][4][4] = {};

    load_chunk(0);
    if (nch > 1) load_chunk(1);

    const int lt = lane >> 3;
    const int lr = lane & 7;
    const int a_row_in = ((lt & 1) << 3) + lr;
    const int a_k16 = lt >> 1;
    const int b_n_in = ((lt >> 1) << 3) + lr;
    const int b_k16 = lt & 1;

    for (int i = 0; i < nch; ++i) {
        if (i + 2 < nch) load_chunk(i + 2);
        cp_wait(min(nch - 1 - i, 2));
        __syncthreads();

        const uint32_t s0 = sb + (uint32_t)(i % NSTAGE) * STAGE_B;
        #pragma unroll
        for (int ks = 0; ks < 2; ++ks) {
            uint32_t afh[4][4], bfh[2][4], tf[4][4];
            const int ck = ks * 2;
            // A hi frags (m64)
            #pragma unroll
            for (int mi = 0; mi < 4; ++mi)
                ldm_x4(afh[mi], swz(s0, wm + mi * 16 + a_row_in, ck + a_k16));
            // B hi frags (n32)
            #pragma unroll
            for (int ni = 0; ni < 2; ++ni)
                ldm_x4(bfh[ni], swz(s0 + 2 * TILE_B, wn + ni * 16 + b_n_in, ck + b_k16));
            // hi*hi
            #pragma unroll
            for (int mi = 0; mi < 4; ++mi)
                #pragma unroll
                for (int nj = 0; nj < 4; ++nj)
                    mma_bf16(acc[mi][nj], afh[mi], bfh[nj >> 1][(nj & 1) * 2],
                             bfh[nj >> 1][(nj & 1) * 2 + 1]);
            // B lo frags -> hi*lo
            #pragma unroll
            for (int ni = 0; ni < 2; ++ni)
                ldm_x4(tf[ni], swz(s0 + 3 * TILE_B, wn + ni * 16 + b_n_in, ck + b_k16));
            #pragma unroll
            for (int mi = 0; mi < 4; ++mi)
                #pragma unroll
                for (int nj = 0; nj < 4; ++nj)
                    mma_bf16(acc[mi][nj], afh[mi], tf[nj >> 1][(nj & 1) * 2],
                             tf[nj >> 1][(nj & 1) * 2 + 1]);
            // A lo frags -> lo*hi
            #pragma unroll
            for (int mi = 0; mi < 4; ++mi)
                ldm_x4(tf[mi], swz(s0 + TILE_B, wm + mi * 16 + a_row_in, ck + a_k16));
            #pragma unroll
            for (int mi = 0; mi < 4; ++mi)
                #pragma unroll
                for (int nj = 0; nj < 4; ++nj)
                    mma_bf16(acc[mi][nj], tf[mi], bfh[nj >> 1][(nj & 1) * 2],
                             bfh[nj >> 1][(nj & 1) * 2 + 1]);
        }
        __syncthreads();
    }

    const int er = lane >> 2;
    const int ec = (lane & 3) * 2;
    #pragma unroll
    for (int mi = 0; mi < 4; ++mi) {
        #pragma unroll
        for (int nj = 0; nj < 4; ++nj) {
            int col = bn + wn + nj * 8 + ec;
            float b0 = bias[col], b1 = bias[col + 1];
            int r0 = bm + wm + mi * 16 + er;
            float2 v0 = make_float2(acc[mi][nj][0] + b0, acc[mi][nj][1] + b1);
            float2 v1 = make_float2(acc[mi][nj][2] + b0, acc[mi][nj][3] + b1);
            *(float2*)&C[(size_t)r0 * N + col] = v0;
            *(float2*)&C[(size_t)(r0 + 8) * N + col] = v1;
        }
    }
}

// ---------------- attention: blocked f32x2, one CTA per (head, window) ----
#define QKP 34
__global__ __launch_bounds__(256)
void attn_kernel(const float* __restrict__ mask,
                 const float* __restrict__ logit_scale) {
    const int h = blockIdx.x;
    const int win = blockIdx.y;
    __shared__ float qs[64][QKP];
    __shared__ float ks[64][QKP];
    __shared__ float vs[64][QKP];
    __shared__ float S[64][65];
    const int tid = threadIdx.x;

    const size_t base = (size_t)win * 64 * QKVN + h * HDIM;
    #pragma unroll
    for (int l = 0; l < 2; ++l) {
        int t = tid + l * 256;
        int n = t >> 3;
        int f = (t & 7) << 2;
        const float* rowp = &g_qkv[base + (size_t)n * QKVN];
        float4 qv = *(const float4*)&rowp[f];
        float4 kv = *(const float4*)&rowp[512 + f];
        float4 vv = *(const float4*)&rowp[1024 + f];
        *(float2*)&qs[n][f]     = make_float2(qv.x, qv.y);
        *(float2*)&qs[n][f + 2] = make_float2(qv.z, qv.w);
        *(float2*)&ks[n][f]     = make_float2(kv.x, kv.y);
        *(float2*)&ks[n][f + 2] = make_float2(kv.z, kv.w);
        *(float2*)&vs[n][f]     = make_float2(vv.x, vv.y);
        *(float2*)&vs[n][f + 2] = make_float2(vv.z, vv.w);
    }
    float scale = fexp(fminf(logit_scale[h], LOGMAX));
    __syncthreads();

    {
        int r = tid >> 1;
        int half = tid & 1;
        float* row = (r < 64) ? qs[r] : ks[r - 64];
        float ss = 0.f;
        #pragma unroll
        for (int d2 = 0; d2 < 16; d2 += 2) {
            float2 v = *(float2*)&row[half * 16 + d2];
            ss += v.x * v.x + v.y * v.y;
        }
        ss += __shfl_xor_sync(0xffffffffu, ss, 1);
        float inv = rsqrtf(ss);
        if (r < 64) inv *= scale;
        #pragma unroll
        for (int d = 0; d < 16; ++d) row[half * 16 + d] *= inv;
    }
    __syncthreads();

    const int ty = tid >> 4, tx = tid & 15;
    unsigned long long a2[4][4];
    #pragma unroll
    for (int ii = 0; ii < 4; ++ii)
        #pragma unroll
        for (int jj = 0; jj < 4; ++jj) a2[ii][jj] = 0ull;
    #pragma unroll
    for (int d2 = 0; d2 < 16; ++d2) {
        unsigned long long q2[4], k2[4];
        #pragma unroll
        for (int ii = 0; ii < 4; ++ii)
            q2[ii] = *(unsigned long long*)&qs[4 * ty + ii][2 * d2];
        #pragma unroll
        for (int jj = 0; jj < 4; ++jj)
            k2[jj] = *(unsigned long long*)&ks[tx + 16 * jj][2 * d2];
        #pragma unroll
        for (int ii = 0; ii < 4; ++ii)
            #pragma unroll
            for (int jj = 0; jj < 4; ++jj)
                ffma2(a2[ii][jj], q2[ii], k2[jj]);
    }
    const float* bias_h = &g_bias[h * 4096];
    const float* mask_w = &mask[(size_t)(win & (NWMASK - 1)) * 4096];
    float sv[4][4];
    #pragma unroll
    for (int ii = 0; ii < 4; ++ii) {
        int r = 4 * ty + ii;
        #pragma unroll
        for (int jj = 0; jj < 4; ++jj) {
            int c = tx + 16 * jj;
            float x, y;
            unpack2(a2[ii][jj], x, y);
            sv[ii][jj] = x + y + bias_h[r * 64 + c] + mask_w[r * 64 + c];
        }
    }
    float sr[4];
    #pragma unroll
    for (int ii = 0; ii < 4; ++ii) {
        float m = fmaxf(fmaxf(sv[ii][0], sv[ii][1]), fmaxf(sv[ii][2], sv[ii][3]));
        m = fmaxf(m, __shfl_xor_sync(0xffffffffu, m, 1));
        m = fmaxf(m, __shfl_xor_sync(0xffffffffu, m, 2));
        m = fmaxf(m, __shfl_xor_sync(0xffffffffu, m, 4));
        m = fmaxf(m, __shfl_xor_sync(0xffffffffu, m, 8));
        float s = 0.f;
        #pragma unroll
        for (int jj = 0; jj < 4; ++jj) {
            sv[ii][jj] = fexp(sv[ii][jj] - m);
            s += sv[ii][jj];
        }
        s += __shfl_xor_sync(0xffffffffu, s, 1);
        s += __shfl_xor_sync(0xffffffffu, s, 2);
        s += __shfl_xor_sync(0xffffffffu, s, 4);
        s += __shfl_xor_sync(0xffffffffu, s, 8);
        sr[ii] = __frcp_rn(s);
    }
    #pragma unroll
    for (int ii = 0; ii < 4; ++ii)
        #pragma unroll
        for (int jj = 0; jj < 4; ++jj)
            S[4 * ty + ii][tx + 16 * jj] = sv[ii][jj] * sr[ii];
    __syncthreads();

    const int ti = ty, tu = tx;
    unsigned long long pa[4] = {0ull, 0ull, 0ull, 0ull};
    #pragma unroll 4
    for (int j = 0; j < 64; ++j) {
        unsigned long long v2 = *(unsigned long long*)&vs[j][2 * tu];
        #pragma unroll
        for (int ii = 0; ii < 4; ++ii) {
            float p = S[4 * ti + ii][j];
            ffma2(pa[ii], pack2(p, p), v2);
        }
    }
    #pragma unroll
    for (int ii = 0; ii < 4; ++ii) {
        float x, y;
        unpack2(pa[ii], x, y);
        size_t orow = ((size_t)win * 64 + 4 * ti + ii) * CHANS + h * HDIM + 2 * tu;
        __nv_bfloat16 hx, lx, hy, ly;
        split1(x, hx, lx);
        split1(y, hy, ly);
        __nv_bfloat162 hv, lv;
        hv.x = hx; hv.y = hy;
        lv.x = lx; lv.y = ly;
        *(__nv_bfloat162*)&g_ao_hi[orow] = hv;
        *(__nv_bfloat162*)&g_ao_lo[orow] = lv;
    }
}

// ---------------- launch ----------------
extern "C" void kernel_launch(void* const* d_in, const int* in_sizes, int n_in,
                              void* d_out, int out_size) {
    const float* x       = (const float*)d_in[0];
    const float* mask    = (const float*)d_in[1];
    const float* rel_t   = (const float*)d_in[2];
    const float* w_qkv   = (const float*)d_in[3];
    const float* q_bias  = (const float*)d_in[4];
    const float* v_bias  = (const float*)d_in[5];
    const float* lscale  = (const float*)d_in[6];
    const float* cpb_w1  = (const float*)d_in[7];
    const float* cpb_b1  = (const float*)d_in[8];
    const float* cpb_w2  = (const float*)d_in[9];
    const float* proj_w  = (const float*)d_in[10];
    const float* proj_b  = (const float*)d_in[11];
    float* out = (float*)d_out;

    void *p_qkv, *p_qb, *p_xh, *p_xl, *p_aoh, *p_aol, *p_wqh, *p_wql, *p_wph, *p_wpl;
    cudaGetSymbolAddress(&p_qkv, g_qkv);
    cudaGetSymbolAddress(&p_qb, g_qkv_bias);
    cudaGetSymbolAddress(&p_xh, g_x_hi);
    cudaGetSymbolAddress(&p_xl, g_x_lo);
    cudaGetSymbolAddress(&p_aoh, g_ao_hi);
    cudaGetSymbolAddress(&p_aol, g_ao_lo);
    cudaGetSymbolAddress(&p_wqh, g_wq_hi);
    cudaGetSymbolAddress(&p_wql, g_wq_lo);
    cudaGetSymbolAddress(&p_wph, g_wp_hi);
    cudaGetSymbolAddress(&p_wpl, g_wp_lo);

    cudaFuncSetAttribute(hmma_gemm, cudaFuncAttributeMaxDynamicSharedMemorySize, GEMM_SMEM);

    qkvbias_kernel<<<6, 256>>>(q_bias, v_bias);
    cpb_table_kernel<<<225, 512>>>(rel_t, cpb_w1, cpb_b1, cpb_w2);
    bias_expand_kernel<<<256, 256>>>();

    split_x_kernel<<<(MROWS * CHANS) / 1024, 256>>>(x);
    wsplit_kernel<<<(CHANS * QKVN + 255) / 256, 256>>>(
        w_qkv, (__nv_bfloat16*)p_wqh, (__nv_bfloat16*)p_wql, CHANS, QKVN);
    wsplit_kernel<<<(CHANS * CHANS + 255) / 256, 256>>>(
        proj_w, (__nv_bfloat16*)p_wph, (__nv_bfloat16*)p_wpl, CHANS, CHANS);

    // QKV: [131072,512] @ [512,1536]
    hmma_gemm<<<dim3(QKVN / 128, MROWS / 128), 256, GEMM_SMEM>>>(
        (const __nv_bfloat16*)p_xh, (const __nv_bfloat16*)p_xl,
        (const __nv_bfloat16*)p_wqh, (const __nv_bfloat16*)p_wql,
        (const float*)p_qb, (float*)p_qkv, MROWS, QKVN, CHANS);

    attn_kernel<<<dim3(NHEAD, BWIN), 256>>>(mask, lscale);

    // proj: [131072,512] @ [512,512]
    hmma_gemm<<<dim3(CHANS / 128, MROWS / 128), 256, GEMM_SMEM>>>(
        (const __nv_bfloat16*)p_aoh, (const __nv_bfloat16*)p_aol,
        (const __nv_bfloat16*)p_wph, (const __nv_bfloat16*)p_wpl,
        proj_b, out, MROWS, CHANS, CHANS);
}

// round 9
// speedup vs baseline: 1.2035x; 1.0109x over previous
#include <cuda_runtime.h>
#include <cuda_bf16.h>
#include <math.h>
#include <stdint.h>

// ---------------- problem constants ----------------
#define BWIN   2048
#define NTOK   64
#define CHANS  512
#define NHEAD  16
#define HDIM   32
#define NWMASK 256
#define MROWS  (BWIN * NTOK)     // 131072
#define QKVN   (3 * CHANS)       // 1536
#define LOGMAX 4.6051701859880914f

// ---------------- scratch ----------------
__device__ float g_qkv[(size_t)MROWS * QKVN];
__device__ __nv_bfloat16 g_x_hi[(size_t)MROWS * CHANS];
__device__ __nv_bfloat16 g_x_lo[(size_t)MROWS * CHANS];
__device__ __nv_bfloat16 g_ao_hi[(size_t)MROWS * CHANS];
__device__ __nv_bfloat16 g_ao_lo[(size_t)MROWS * CHANS];
__device__ __nv_bfloat16 g_wq_hi[(size_t)QKVN * CHANS];   // [N,K] transposed
__device__ __nv_bfloat16 g_wq_lo[(size_t)QKVN * CHANS];
__device__ __nv_bfloat16 g_wp_hi[(size_t)CHANS * CHANS];
__device__ __nv_bfloat16 g_wp_lo[(size_t)CHANS * CHANS];
__device__ float g_table[225 * NHEAD];
__device__ float g_bias[NHEAD * NTOK * NTOK];
__device__ float g_qkv_bias[QKVN];

// ---------------- helpers ----------------
__device__ __forceinline__ uint32_t smem_u32(const void* p) {
    uint32_t a;
    asm("{ .reg .u64 t; cvta.to.shared.u64 t, %1; cvt.u32.u64 %0, t; }" : "=r"(a) : "l"(p));
    return a;
}
__device__ __forceinline__ void cp16(uint32_t dst, const void* src) {
    asm volatile("cp.async.cg.shared.global [%0], [%1], 16;" :: "r"(dst), "l"(src));
}
#define CP_COMMIT() asm volatile("cp.async.commit_group;" ::: "memory")
__device__ __forceinline__ void cp_wait(int rem) {
    if (rem >= 1) asm volatile("cp.async.wait_group 1;" ::: "memory");
    else          asm volatile("cp.async.wait_group 0;" ::: "memory");
}
__device__ __forceinline__ void ldm_x4(uint32_t* r, uint32_t addr) {
    asm volatile("ldmatrix.sync.aligned.m8n8.x4.shared.b16 {%0,%1,%2,%3}, [%4];"
                 : "=r"(r[0]), "=r"(r[1]), "=r"(r[2]), "=r"(r[3]) : "r"(addr));
}
__device__ __forceinline__ void mma_bf16(float* d, const uint32_t* a, uint32_t b0, uint32_t b1) {
    asm volatile(
        "mma.sync.aligned.m16n8k16.row.col.f32.bf16.bf16.f32 "
        "{%0,%1,%2,%3}, {%4,%5,%6,%7}, {%8,%9}, {%0,%1,%2,%3};"
        : "+f"(d[0]), "+f"(d[1]), "+f"(d[2]), "+f"(d[3])
        : "r"(a[0]), "r"(a[1]), "r"(a[2]), "r"(a[3]), "r"(b0), "r"(b1));
}
__device__ __forceinline__ void split1(float x, __nv_bfloat16& h, __nv_bfloat16& l) {
    h = __float2bfloat16(x);
    l = __float2bfloat16(x - __bfloat162float(h));
}
// packed f32x2 FMA (Blackwell FFMA2, PTX-only)
__device__ __forceinline__ void ffma2(unsigned long long& d,
                                      unsigned long long a, unsigned long long b) {
    asm("fma.rn.f32x2 %0, %1, %2, %0;" : "+l"(d) : "l"(a), "l"(b));
}
__device__ __forceinline__ unsigned long long pack2(float x, float y) {
    unsigned long long r;
    asm("mov.b64 %0, {%1, %2};" : "=l"(r) : "f"(x), "f"(y));
    return r;
}
__device__ __forceinline__ void unpack2(unsigned long long v, float& x, float& y) {
    asm("mov.b64 {%0, %1}, %2;" : "=f"(x), "=f"(y) : "l"(v));
}
// fast exp via FMA polynomial (no MUFU)
__device__ __forceinline__ float fexp(float x) {
    float t = fmaxf(x * 1.442695040888963f, -125.f);
    float n = rintf(t);
    float f = t - n;
    float p = 1.3392138e-3f;
    p = fmaf(p, f, 9.6181291e-3f);
    p = fmaf(p, f, 5.5504108e-2f);
    p = fmaf(p, f, 2.4022650e-1f);
    p = fmaf(p, f, 6.9314718e-1f);
    p = fmaf(p, f, 1.0f);
    return __int_as_float(((int)n + 127) << 23) * p;
}

// ---------------- tiny prep kernels ----------------
__global__ void qkvbias_kernel(const float* __restrict__ qb,
                               const float* __restrict__ vb) {
    int n = blockIdx.x * 256 + threadIdx.x;
    if (n >= QKVN) return;
    float v = 0.f;
    if (n < CHANS) v = qb[n];
    else if (n >= 2 * CHANS) v = vb[n - 2 * CHANS];
    g_qkv_bias[n] = v;
}

__global__ void cpb_table_kernel(const float* __restrict__ rel_table,
                                 const float* __restrict__ w1,
                                 const float* __restrict__ b1,
                                 const float* __restrict__ w2) {
    int p = blockIdx.x;
    int j = threadIdx.x;
    __shared__ float hid[512];
    float t0 = rel_table[p * 2 + 0];
    float t1 = rel_table[p * 2 + 1];
    hid[j] = fmaxf(t0 * w1[j] + t1 * w1[512 + j] + b1[j], 0.f);
    __syncthreads();
    if (j < NHEAD) {
        float acc = 0.f;
        #pragma unroll 8
        for (int r = 0; r < 512; ++r) acc += hid[r] * w2[r * NHEAD + j];
        g_table[p * NHEAD + j] = acc;
    }
}

__global__ void bias_expand_kernel() {
    int id = blockIdx.x * 256 + threadIdx.x;
    int h = id >> 12;
    int i = (id >> 6) & 63;
    int j = id & 63;
    int idx = ((i >> 3) - (j >> 3) + 7) * 15 + ((i & 7) - (j & 7) + 7);
    float b = g_table[idx * NHEAD + h];
    g_bias[id] = 16.f / (1.f + fexp(-b));
}

__global__ void split_x_kernel(const float* __restrict__ src) {
    size_t i = ((size_t)blockIdx.x * 256 + threadIdx.x) * 4;
    float4 v = *(const float4*)&src[i];
    __align__(8) __nv_bfloat16 h[4], l[4];
    split1(v.x, h[0], l[0]);
    split1(v.y, h[1], l[1]);
    split1(v.z, h[2], l[2]);
    split1(v.w, h[3], l[3]);
    *(uint2*)&g_x_hi[i] = *(uint2*)h;
    *(uint2*)&g_x_lo[i] = *(uint2*)l;
}

__global__ void wsplit_kernel(const float* __restrict__ w,
                              __nv_bfloat16* __restrict__ hiT,
                              __nv_bfloat16* __restrict__ loT,
                              int K, int N) {
    int idx = blockIdx.x * 256 + threadIdx.x;
    if (idx >= K * N) return;
    int k = idx / N, n = idx % N;
    __nv_bfloat16 h, l;
    split1(w[idx], h, l);
    hiT[(size_t)n * K + k] = h;
    loT[(size_t)n * K + k] = l;
}

// ---------------- HMMA bf16x3 GEMM ----------------
// C[M,N] = (Ahi+Alo)[M,K] @ (Bhi+Blo)[N,K]^T + bias[N]
// BM=128 BN=128 BK=32, 256 thr / 8 warps (2Mx4N), warp tile 64x32,
// XOR-swizzled 64B rows, 3-stage cp.async, ONE barrier per chunk.
#define TILE_B 8192                      // 128 rows x 64 B
#define STAGE_B (4 * TILE_B)             // 32768 B
#define NSTAGE 3
#define GEMM_SMEM (NSTAGE * STAGE_B)     // 98304 B

__device__ __forceinline__ uint32_t swz(uint32_t tile, int row, int chunk) {
    return tile + row * 64 + (((chunk + (row >> 1)) & 3) << 4);
}

__global__ void __launch_bounds__(256, 2)
hmma_gemm(const __nv_bfloat16* __restrict__ Ahi, const __nv_bfloat16* __restrict__ Alo,
          const __nv_bfloat16* __restrict__ Bhi, const __nv_bfloat16* __restrict__ Blo,
          const float* __restrict__ bias, float* __restrict__ C,
          int M, int N, int K) {
    extern __shared__ char smem[];
    const uint32_t sb = smem_u32(smem);
    const int tid = threadIdx.x;
    const int wid = tid >> 5, lane = tid & 31;
    const int bm = blockIdx.y * 128;
    const int bn = blockIdx.x * 128;
    const int wm = (wid >> 2) * 64;
    const int wn = (wid & 3) * 32;
    const int nch = K >> 5;

    auto load_tile = [&](const __nv_bfloat16* g, int rowbase, int k0, uint32_t off) {
        #pragma unroll
        for (int c = tid; c < 512; c += 256) {
            int row = c >> 2, chunk = c & 3;
            cp16(swz(sb + off, row, chunk),
                 g + (size_t)(rowbase + row) * K + k0 + chunk * 8);
        }
    };
    auto load_chunk = [&](int chunk) {
        int k0 = chunk << 5;
        uint32_t s0 = (uint32_t)(chunk % NSTAGE) * STAGE_B;
        load_tile(Ahi, bm, k0, s0);
        load_tile(Alo, bm, k0, s0 + TILE_B);
        load_tile(Bhi, bn, k0, s0 + 2 * TILE_B);
        load_tile(Blo, bn, k0, s0 + 3 * TILE_B);
        CP_COMMIT();
    };

    float acc[4][4][4] = {};

    load_chunk(0);
    if (nch > 1) load_chunk(1);

    const int lt = lane >> 3;
    const int lr = lane & 7;
    const int a_row_in = ((lt & 1) << 3) + lr;
    const int a_k16 = lt >> 1;
    const int b_n_in = ((lt >> 1) << 3) + lr;
    const int b_k16 = lt & 1;

    for (int i = 0; i < nch; ++i) {
        // wait for stage i (allow the one younger in-flight group), then one
        // barrier; the barrier also proves everyone finished compute of i-1,
        // making stage (i+2)%3 == (i-1)%3 safe to overwrite.
        cp_wait(i + 1 < nch ? 1 : 0);
        __syncthreads();
        if (i + 2 < nch) load_chunk(i + 2);

        const uint32_t s0 = sb + (uint32_t)(i % NSTAGE) * STAGE_B;
        #pragma unroll
        for (int ks = 0; ks < 2; ++ks) {
            uint32_t afh[4][4], bfh[2][4], tf[4][4];
            const int ck = ks * 2;
            // A hi frags (m64)
            #pragma unroll
            for (int mi = 0; mi < 4; ++mi)
                ldm_x4(afh[mi], swz(s0, wm + mi * 16 + a_row_in, ck + a_k16));
            // B hi frags (n32)
            #pragma unroll
            for (int ni = 0; ni < 2; ++ni)
                ldm_x4(bfh[ni], swz(s0 + 2 * TILE_B, wn + ni * 16 + b_n_in, ck + b_k16));
            // hi*hi
            #pragma unroll
            for (int mi = 0; mi < 4; ++mi)
                #pragma unroll
                for (int nj = 0; nj < 4; ++nj)
                    mma_bf16(acc[mi][nj], afh[mi], bfh[nj >> 1][(nj & 1) * 2],
                             bfh[nj >> 1][(nj & 1) * 2 + 1]);
            // B lo frags -> hi*lo
            #pragma unroll
            for (int ni = 0; ni < 2; ++ni)
                ldm_x4(tf[ni], swz(s0 + 3 * TILE_B, wn + ni * 16 + b_n_in, ck + b_k16));
            #pragma unroll
            for (int mi = 0; mi < 4; ++mi)
                #pragma unroll
                for (int nj = 0; nj < 4; ++nj)
                    mma_bf16(acc[mi][nj], afh[mi], tf[nj >> 1][(nj & 1) * 2],
                             tf[nj >> 1][(nj & 1) * 2 + 1]);
            // A lo frags -> lo*hi
            #pragma unroll
            for (int mi = 0; mi < 4; ++mi)
                ldm_x4(tf[mi], swz(s0 + TILE_B, wm + mi * 16 + a_row_in, ck + a_k16));
            #pragma unroll
            for (int mi = 0; mi < 4; ++mi)
                #pragma unroll
                for (int nj = 0; nj < 4; ++nj)
                    mma_bf16(acc[mi][nj], tf[mi], bfh[nj >> 1][(nj & 1) * 2],
                             bfh[nj >> 1][(nj & 1) * 2 + 1]);
        }
    }

    const int er = lane >> 2;
    const int ec = (lane & 3) * 2;
    #pragma unroll
    for (int mi = 0; mi < 4; ++mi) {
        #pragma unroll
        for (int nj = 0; nj < 4; ++nj) {
            int col = bn + wn + nj * 8 + ec;
            float b0 = bias[col], b1 = bias[col + 1];
            int r0 = bm + wm + mi * 16 + er;
            float2 v0 = make_float2(acc[mi][nj][0] + b0, acc[mi][nj][1] + b1);
            float2 v1 = make_float2(acc[mi][nj][2] + b0, acc[mi][nj][3] + b1);
            *(float2*)&C[(size_t)r0 * N + col] = v0;
            *(float2*)&C[(size_t)(r0 + 8) * N + col] = v1;
        }
    }
}

// ---------------- attention: blocked f32x2, one CTA per (head, window) ----
#define QKP 34
__global__ __launch_bounds__(256)
void attn_kernel(const float* __restrict__ mask,
                 const float* __restrict__ logit_scale) {
    const int h = blockIdx.x;
    const int win = blockIdx.y;
    __shared__ float qs[64][QKP];
    __shared__ float ks[64][QKP];
    __shared__ float vs[64][QKP];
    __shared__ float S[64][65];
    const int tid = threadIdx.x;

    const size_t base = (size_t)win * 64 * QKVN + h * HDIM;
    #pragma unroll
    for (int l = 0; l < 2; ++l) {
        int t = tid + l * 256;
        int n = t >> 3;
        int f = (t & 7) << 2;
        const float* rowp = &g_qkv[base + (size_t)n * QKVN];
        float4 qv = *(const float4*)&rowp[f];
        float4 kv = *(const float4*)&rowp[512 + f];
        float4 vv = *(const float4*)&rowp[1024 + f];
        *(float2*)&qs[n][f]     = make_float2(qv.x, qv.y);
        *(float2*)&qs[n][f + 2] = make_float2(qv.z, qv.w);
        *(float2*)&ks[n][f]     = make_float2(kv.x, kv.y);
        *(float2*)&ks[n][f + 2] = make_float2(kv.z, kv.w);
        *(float2*)&vs[n][f]     = make_float2(vv.x, vv.y);
        *(float2*)&vs[n][f + 2] = make_float2(vv.z, vv.w);
    }
    float scale = fexp(fminf(logit_scale[h], LOGMAX));
    __syncthreads();

    {
        int r = tid >> 1;
        int half = tid & 1;
        float* row = (r < 64) ? qs[r] : ks[r - 64];
        float ss = 0.f;
        #pragma unroll
        for (int d2 = 0; d2 < 16; d2 += 2) {
            float2 v = *(float2*)&row[half * 16 + d2];
            ss += v.x * v.x + v.y * v.y;
        }
        ss += __shfl_xor_sync(0xffffffffu, ss, 1);
        float inv = rsqrtf(ss);
        if (r < 64) inv *= scale;
        #pragma unroll
        for (int d = 0; d < 16; ++d) row[half * 16 + d] *= inv;
    }
    __syncthreads();

    const int ty = tid >> 4, tx = tid & 15;
    unsigned long long a2[4][4];
    #pragma unroll
    for (int ii = 0; ii < 4; ++ii)
        #pragma unroll
        for (int jj = 0; jj < 4; ++jj) a2[ii][jj] = 0ull;
    #pragma unroll
    for (int d2 = 0; d2 < 16; ++d2) {
        unsigned long long q2[4], k2[4];
        #pragma unroll
        for (int ii = 0; ii < 4; ++ii)
            q2[ii] = *(unsigned long long*)&qs[4 * ty + ii][2 * d2];
        #pragma unroll
        for (int jj = 0; jj < 4; ++jj)
            k2[jj] = *(unsigned long long*)&ks[tx + 16 * jj][2 * d2];
        #pragma unroll
        for (int ii = 0; ii < 4; ++ii)
            #pragma unroll
            for (int jj = 0; jj < 4; ++jj)
                ffma2(a2[ii][jj], q2[ii], k2[jj]);
    }
    const float* bias_h = &g_bias[h * 4096];
    const float* mask_w = &mask[(size_t)(win & (NWMASK - 1)) * 4096];
    float sv[4][4];
    #pragma unroll
    for (int ii = 0; ii < 4; ++ii) {
        int r = 4 * ty + ii;
        #pragma unroll
        for (int jj = 0; jj < 4; ++jj) {
            int c = tx + 16 * jj;
            float x, y;
            unpack2(a2[ii][jj], x, y);
            sv[ii][jj] = x + y + bias_h[r * 64 + c] + mask_w[r * 64 + c];
        }
    }
    float sr[4];
    #pragma unroll
    for (int ii = 0; ii < 4; ++ii) {
        float m = fmaxf(fmaxf(sv[ii][0], sv[ii][1]), fmaxf(sv[ii][2], sv[ii][3]));
        m = fmaxf(m, __shfl_xor_sync(0xffffffffu, m, 1));
        m = fmaxf(m, __shfl_xor_sync(0xffffffffu, m, 2));
        m = fmaxf(m, __shfl_xor_sync(0xffffffffu, m, 4));
        m = fmaxf(m, __shfl_xor_sync(0xffffffffu, m, 8));
        float s = 0.f;
        #pragma unroll
        for (int jj = 0; jj < 4; ++jj) {
            sv[ii][jj] = fexp(sv[ii][jj] - m);
            s += sv[ii][jj];
        }
        s += __shfl_xor_sync(0xffffffffu, s, 1);
        s += __shfl_xor_sync(0xffffffffu, s, 2);
        s += __shfl_xor_sync(0xffffffffu, s, 4);
        s += __shfl_xor_sync(0xffffffffu, s, 8);
        sr[ii] = __frcp_rn(s);
    }
    #pragma unroll
    for (int ii = 0; ii < 4; ++ii)
        #pragma unroll
        for (int jj = 0; jj < 4; ++jj)
            S[4 * ty + ii][tx + 16 * jj] = sv[ii][jj] * sr[ii];
    __syncthreads();

    const int ti = ty, tu = tx;
    unsigned long long pa[4] = {0ull, 0ull, 0ull, 0ull};
    #pragma unroll 4
    for (int j = 0; j < 64; ++j) {
        unsigned long long v2 = *(unsigned long long*)&vs[j][2 * tu];
        #pragma unroll
        for (int ii = 0; ii < 4; ++ii) {
            float p = S[4 * ti + ii][j];
            ffma2(pa[ii], pack2(p, p), v2);
        }
    }
    #pragma unroll
    for (int ii = 0; ii < 4; ++ii) {
        float x, y;
        unpack2(pa[ii], x, y);
        size_t orow = ((size_t)win * 64 + 4 * ti + ii) * CHANS + h * HDIM + 2 * tu;
        __nv_bfloat16 hx, lx, hy, ly;
        split1(x, hx, lx);
        split1(y, hy, ly);
        __nv_bfloat162 hv, lv;
        hv.x = hx; hv.y = hy;
        lv.x = lx; lv.y = ly;
        *(__nv_bfloat162*)&g_ao_hi[orow] = hv;
        *(__nv_bfloat162*)&g_ao_lo[orow] = lv;
    }
}

// ---------------- launch ----------------
extern "C" void kernel_launch(void* const* d_in, const int* in_sizes, int n_in,
                              void* d_out, int out_size) {
    const float* x       = (const float*)d_in[0];
    const float* mask    = (const float*)d_in[1];
    const float* rel_t   = (const float*)d_in[2];
    const float* w_qkv   = (const float*)d_in[3];
    const float* q_bias  = (const float*)d_in[4];
    const float* v_bias  = (const float*)d_in[5];
    const float* lscale  = (const float*)d_in[6];
    const float* cpb_w1  = (const float*)d_in[7];
    const float* cpb_b1  = (const float*)d_in[8];
    const float* cpb_w2  = (const float*)d_in[9];
    const float* proj_w  = (const float*)d_in[10];
    const float* proj_b  = (const float*)d_in[11];
    float* out = (float*)d_out;

    void *p_qkv, *p_qb, *p_xh, *p_xl, *p_aoh, *p_aol, *p_wqh, *p_wql, *p_wph, *p_wpl;
    cudaGetSymbolAddress(&p_qkv, g_qkv);
    cudaGetSymbolAddress(&p_qb, g_qkv_bias);
    cudaGetSymbolAddress(&p_xh, g_x_hi);
    cudaGetSymbolAddress(&p_xl, g_x_lo);
    cudaGetSymbolAddress(&p_aoh, g_ao_hi);
    cudaGetSymbolAddress(&p_aol, g_ao_lo);
    cudaGetSymbolAddress(&p_wqh, g_wq_hi);
    cudaGetSymbolAddress(&p_wql, g_wq_lo);
    cudaGetSymbolAddress(&p_wph, g_wp_hi);
    cudaGetSymbolAddress(&p_wpl, g_wp_lo);

    cudaFuncSetAttribute(hmma_gemm, cudaFuncAttributeMaxDynamicSharedMemorySize, GEMM_SMEM);

    qkvbias_kernel<<<6, 256>>>(q_bias, v_bias);
    cpb_table_kernel<<<225, 512>>>(rel_t, cpb_w1, cpb_b1, cpb_w2);
    bias_expand_kernel<<<256, 256>>>();

    split_x_kernel<<<(MROWS * CHANS) / 1024, 256>>>(x);
    wsplit_kernel<<<(CHANS * QKVN + 255) / 256, 256>>>(
        w_qkv, (__nv_bfloat16*)p_wqh, (__nv_bfloat16*)p_wql, CHANS, QKVN);
    wsplit_kernel<<<(CHANS * CHANS + 255) / 256, 256>>>(
        proj_w, (__nv_bfloat16*)p_wph, (__nv_bfloat16*)p_wpl, CHANS, CHANS);

    // QKV: [131072,512] @ [512,1536]
    hmma_gemm<<<dim3(QKVN / 128, MROWS / 128), 256, GEMM_SMEM>>>(
        (const __nv_bfloat16*)p_xh, (const __nv_bfloat16*)p_xl,
        (const __nv_bfloat16*)p_wqh, (const __nv_bfloat16*)p_wql,
        (const float*)p_qb, (float*)p_qkv, MROWS, QKVN, CHANS);

    attn_kernel<<<dim3(NHEAD, BWIN), 256>>>(mask, lscale);

    // proj: [131072,512] @ [512,512]
    hmma_gemm<<<dim3(CHANS / 128, MROWS / 128), 256, GEMM_SMEM>>>(
        (const __nv_bfloat16*)p_aoh, (const __nv_bfloat16*)p_aol,
        (const __nv_bfloat16*)p_wph, (const __nv_bfloat16*)p_wpl,
        proj_b, out, MROWS, CHANS, CHANS);
}

// round 10
// speedup vs baseline: 1.2086x; 1.0042x over previous
#include <cuda_runtime.h>
#include <cuda_bf16.h>
#include <math.h>
#include <stdint.h>

// ---------------- problem constants ----------------
#define BWIN   2048
#define NTOK   64
#define CHANS  512
#define NHEAD  16
#define HDIM   32
#define NWMASK 256
#define MROWS  (BWIN * NTOK)     // 131072
#define QKVN   (3 * CHANS)       // 1536
#define LOGMAX 4.6051701859880914f

// ---------------- scratch ----------------
__device__ float g_qkv[(size_t)MROWS * QKVN];
__device__ __nv_bfloat16 g_x_hi[(size_t)MROWS * CHANS];
__device__ __nv_bfloat16 g_x_lo[(size_t)MROWS * CHANS];
__device__ __nv_bfloat16 g_ao_hi[(size_t)MROWS * CHANS];
__device__ __nv_bfloat16 g_ao_lo[(size_t)MROWS * CHANS];
__device__ __nv_bfloat16 g_wq_hi[(size_t)QKVN * CHANS];   // [N,K] transposed
__device__ __nv_bfloat16 g_wq_lo[(size_t)QKVN * CHANS];
__device__ __nv_bfloat16 g_wp_hi[(size_t)CHANS * CHANS];
__device__ __nv_bfloat16 g_wp_lo[(size_t)CHANS * CHANS];
__device__ float g_table[225 * NHEAD];
__device__ float g_bias[NHEAD * NTOK * NTOK];
__device__ float g_qkv_bias[QKVN];

// ---------------- helpers ----------------
__device__ __forceinline__ uint32_t smem_u32(const void* p) {
    uint32_t a;
    asm("{ .reg .u64 t; cvta.to.shared.u64 t, %1; cvt.u32.u64 %0, t; }" : "=r"(a) : "l"(p));
    return a;
}
__device__ __forceinline__ void cp16(uint32_t dst, const void* src) {
    asm volatile("cp.async.cg.shared.global [%0], [%1], 16;" :: "r"(dst), "l"(src));
}
#define CP_COMMIT() asm volatile("cp.async.commit_group;" ::: "memory")
__device__ __forceinline__ void cp_wait(int rem) {
    if (rem >= 1) asm volatile("cp.async.wait_group 1;" ::: "memory");
    else          asm volatile("cp.async.wait_group 0;" ::: "memory");
}
__device__ __forceinline__ void ldm_x4(uint32_t* r, uint32_t addr) {
    asm volatile("ldmatrix.sync.aligned.m8n8.x4.shared.b16 {%0,%1,%2,%3}, [%4];"
                 : "=r"(r[0]), "=r"(r[1]), "=r"(r[2]), "=r"(r[3]) : "r"(addr));
}
__device__ __forceinline__ void mma_bf16(float* d, const uint32_t* a, uint32_t b0, uint32_t b1) {
    asm volatile(
        "mma.sync.aligned.m16n8k16.row.col.f32.bf16.bf16.f32 "
        "{%0,%1,%2,%3}, {%4,%5,%6,%7}, {%8,%9}, {%0,%1,%2,%3};"
        : "+f"(d[0]), "+f"(d[1]), "+f"(d[2]), "+f"(d[3])
        : "r"(a[0]), "r"(a[1]), "r"(a[2]), "r"(a[3]), "r"(b0), "r"(b1));
}
__device__ __forceinline__ void split1(float x, __nv_bfloat16& h, __nv_bfloat16& l) {
    h = __float2bfloat16(x);
    l = __float2bfloat16(x - __bfloat162float(h));
}
// packed f32x2 FMA (Blackwell FFMA2, PTX-only)
__device__ __forceinline__ void ffma2(unsigned long long& d,
                                      unsigned long long a, unsigned long long b) {
    asm("fma.rn.f32x2 %0, %1, %2, %0;" : "+l"(d) : "l"(a), "l"(b));
}
__device__ __forceinline__ unsigned long long pack2(float x, float y) {
    unsigned long long r;
    asm("mov.b64 %0, {%1, %2};" : "=l"(r) : "f"(x), "f"(y));
    return r;
}
__device__ __forceinline__ void unpack2(unsigned long long v, float& x, float& y) {
    asm("mov.b64 {%0, %1}, %2;" : "=f"(x), "=f"(y) : "l"(v));
}
// fast exp via FMA polynomial (no MUFU)
__device__ __forceinline__ float fexp(float x) {
    float t = fmaxf(x * 1.442695040888963f, -125.f);
    float n = rintf(t);
    float f = t - n;
    float p = 1.3392138e-3f;
    p = fmaf(p, f, 9.6181291e-3f);
    p = fmaf(p, f, 5.5504108e-2f);
    p = fmaf(p, f, 2.4022650e-1f);
    p = fmaf(p, f, 6.9314718e-1f);
    p = fmaf(p, f, 1.0f);
    return __int_as_float(((int)n + 127) << 23) * p;
}

// ---------------- tiny prep kernels ----------------
__global__ void qkvbias_kernel(const float* __restrict__ qb,
                               const float* __restrict__ vb) {
    int n = blockIdx.x * 256 + threadIdx.x;
    if (n >= QKVN) return;
    float v = 0.f;
    if (n < CHANS) v = qb[n];
    else if (n >= 2 * CHANS) v = vb[n - 2 * CHANS];
    g_qkv_bias[n] = v;
}

__global__ void cpb_table_kernel(const float* __restrict__ rel_table,
                                 const float* __restrict__ w1,
                                 const float* __restrict__ b1,
                                 const float* __restrict__ w2) {
    int p = blockIdx.x;
    int j = threadIdx.x;
    __shared__ float hid[512];
    float t0 = rel_table[p * 2 + 0];
    float t1 = rel_table[p * 2 + 1];
    hid[j] = fmaxf(t0 * w1[j] + t1 * w1[512 + j] + b1[j], 0.f);
    __syncthreads();
    if (j < NHEAD) {
        float acc = 0.f;
        #pragma unroll 8
        for (int r = 0; r < 512; ++r) acc += hid[r] * w2[r * NHEAD + j];
        g_table[p * NHEAD + j] = acc;
    }
}

__global__ void bias_expand_kernel() {
    int id = blockIdx.x * 256 + threadIdx.x;
    int h = id >> 12;
    int i = (id >> 6) & 63;
    int j = id & 63;
    int idx = ((i >> 3) - (j >> 3) + 7) * 15 + ((i & 7) - (j & 7) + 7);
    float b = g_table[idx * NHEAD + h];
    g_bias[id] = 16.f / (1.f + fexp(-b));
}

__global__ void split_x_kernel(const float* __restrict__ src) {
    size_t i = ((size_t)blockIdx.x * 256 + threadIdx.x) * 4;
    float4 v = *(const float4*)&src[i];
    __align__(8) __nv_bfloat16 h[4], l[4];
    split1(v.x, h[0], l[0]);
    split1(v.y, h[1], l[1]);
    split1(v.z, h[2], l[2]);
    split1(v.w, h[3], l[3]);
    *(uint2*)&g_x_hi[i] = *(uint2*)h;
    *(uint2*)&g_x_lo[i] = *(uint2*)l;
}

__global__ void wsplit_kernel(const float* __restrict__ w,
                              __nv_bfloat16* __restrict__ hiT,
                              __nv_bfloat16* __restrict__ loT,
                              int K, int N) {
    int idx = blockIdx.x * 256 + threadIdx.x;
    if (idx >= K * N) return;
    int k = idx / N, n = idx % N;
    __nv_bfloat16 h, l;
    split1(w[idx], h, l);
    hiT[(size_t)n * K + k] = h;
    loT[(size_t)n * K + k] = l;
}

// ---------------- HMMA bf16x3 GEMM ----------------
// C[M,N] = (Ahi+Alo)[M,K] @ (Bhi+Blo)[N,K]^T + bias[N]
// BM=128 BN=128 BK=32, 256 thr / 8 warps (2Mx4N), warp tile 64x32,
// XOR-swizzled 64B rows, 3-stage cp.async, one barrier per chunk,
// warp-parity ks-stagger to decorrelate LDSM phases across warps.
#define TILE_B 8192                      // 128 rows x 64 B
#define STAGE_B (4 * TILE_B)             // 32768 B
#define NSTAGE 3
#define GEMM_SMEM (NSTAGE * STAGE_B)     // 98304 B

__device__ __forceinline__ uint32_t swz(uint32_t tile, int row, int chunk) {
    return tile + row * 64 + (((chunk + (row >> 1)) & 3) << 4);
}

__global__ void __launch_bounds__(256, 2)
hmma_gemm(const __nv_bfloat16* __restrict__ Ahi, const __nv_bfloat16* __restrict__ Alo,
          const __nv_bfloat16* __restrict__ Bhi, const __nv_bfloat16* __restrict__ Blo,
          const float* __restrict__ bias, float* __restrict__ C,
          int M, int N, int K) {
    extern __shared__ char smem[];
    const uint32_t sb = smem_u32(smem);
    const int tid = threadIdx.x;
    const int wid = tid >> 5, lane = tid & 31;
    const int bm = blockIdx.y * 128;
    const int bn = blockIdx.x * 128;
    const int wm = (wid >> 2) * 64;
    const int wn = (wid & 3) * 32;
    const int nch = K >> 5;
    const int ks_flip = wid & 1;         // stagger: odd warps run ks=1 first

    auto load_tile = [&](const __nv_bfloat16* g, int rowbase, int k0, uint32_t off) {
        #pragma unroll
        for (int c = tid; c < 512; c += 256) {
            int row = c >> 2, chunk = c & 3;
            cp16(swz(sb + off, row, chunk),
                 g + (size_t)(rowbase + row) * K + k0 + chunk * 8);
        }
    };
    auto load_chunk = [&](int chunk) {
        int k0 = chunk << 5;
        uint32_t s0 = (uint32_t)(chunk % NSTAGE) * STAGE_B;
        load_tile(Ahi, bm, k0, s0);
        load_tile(Alo, bm, k0, s0 + TILE_B);
        load_tile(Bhi, bn, k0, s0 + 2 * TILE_B);
        load_tile(Blo, bn, k0, s0 + 3 * TILE_B);
        CP_COMMIT();
    };

    float acc[4][4][4] = {};

    load_chunk(0);
    if (nch > 1) load_chunk(1);

    const int lt = lane >> 3;
    const int lr = lane & 7;
    const int a_row_in = ((lt & 1) << 3) + lr;
    const int a_k16 = lt >> 1;
    const int b_n_in = ((lt >> 1) << 3) + lr;
    const int b_k16 = lt & 1;

    for (int i = 0; i < nch; ++i) {
        cp_wait(i + 1 < nch ? 1 : 0);
        __syncthreads();
        if (i + 2 < nch) load_chunk(i + 2);

        const uint32_t s0 = sb + (uint32_t)(i % NSTAGE) * STAGE_B;
        #pragma unroll
        for (int ks2 = 0; ks2 < 2; ++ks2) {
            const int ks = ks2 ^ ks_flip;   // warp-parity stagger
            uint32_t afh[4][4], bfh[2][4], tf[4][4];
            const int ck = ks * 2;
            // A hi frags (m64)
            #pragma unroll
            for (int mi = 0; mi < 4; ++mi)
                ldm_x4(afh[mi], swz(s0, wm + mi * 16 + a_row_in, ck + a_k16));
            // B hi frags (n32)
            #pragma unroll
            for (int ni = 0; ni < 2; ++ni)
                ldm_x4(bfh[ni], swz(s0 + 2 * TILE_B, wn + ni * 16 + b_n_in, ck + b_k16));
            // hi*hi
            #pragma unroll
            for (int mi = 0; mi < 4; ++mi)
                #pragma unroll
                for (int nj = 0; nj < 4; ++nj)
                    mma_bf16(acc[mi][nj], afh[mi], bfh[nj >> 1][(nj & 1) * 2],
                             bfh[nj >> 1][(nj & 1) * 2 + 1]);
            // B lo frags -> hi*lo
            #pragma unroll
            for (int ni = 0; ni < 2; ++ni)
                ldm_x4(tf[ni], swz(s0 + 3 * TILE_B, wn + ni * 16 + b_n_in, ck + b_k16));
            #pragma unroll
            for (int mi = 0; mi < 4; ++mi)
                #pragma unroll
                for (int nj = 0; nj < 4; ++nj)
                    mma_bf16(acc[mi][nj], afh[mi], tf[nj >> 1][(nj & 1) * 2],
                             tf[nj >> 1][(nj & 1) * 2 + 1]);
            // A lo frags -> lo*hi
            #pragma unroll
            for (int mi = 0; mi < 4; ++mi)
                ldm_x4(tf[mi], swz(s0 + TILE_B, wm + mi * 16 + a_row_in, ck + a_k16));
            #pragma unroll
            for (int mi = 0; mi < 4; ++mi)
                #pragma unroll
                for (int nj = 0; nj < 4; ++nj)
                    mma_bf16(acc[mi][nj], tf[mi], bfh[nj >> 1][(nj & 1) * 2],
                             bfh[nj >> 1][(nj & 1) * 2 + 1]);
        }
    }

    const int er = lane >> 2;
    const int ec = (lane & 3) * 2;
    #pragma unroll
    for (int mi = 0; mi < 4; ++mi) {
        #pragma unroll
        for (int nj = 0; nj < 4; ++nj) {
            int col = bn + wn + nj * 8 + ec;
            float b0 = bias[col], b1 = bias[col + 1];
            int r0 = bm + wm + mi * 16 + er;
            float2 v0 = make_float2(acc[mi][nj][0] + b0, acc[mi][nj][1] + b1);
            float2 v1 = make_float2(acc[mi][nj][2] + b0, acc[mi][nj][3] + b1);
            *(float2*)&C[(size_t)r0 * N + col] = v0;
            *(float2*)&C[(size_t)(r0 + 8) * N + col] = v1;
        }
    }
}

// ---------------- attention: blocked f32x2, one CTA per (head, window) ----
#define QKP 34
#define SP  66   // S row stride (even -> float2-aligned rows)
__global__ __launch_bounds__(256)
void attn_kernel(const float* __restrict__ mask,
                 const float* __restrict__ logit_scale) {
    const int h = blockIdx.x;
    const int win = blockIdx.y;
    __shared__ float qs[64][QKP];
    __shared__ float ks[64][QKP];
    __shared__ float vs[64][QKP];
    __shared__ float S[64][SP];
    const int tid = threadIdx.x;

    const size_t base = (size_t)win * 64 * QKVN + h * HDIM;
    #pragma unroll
    for (int l = 0; l < 2; ++l) {
        int t = tid + l * 256;
        int n = t >> 3;
        int f = (t & 7) << 2;
        const float* rowp = &g_qkv[base + (size_t)n * QKVN];
        float4 qv = *(const float4*)&rowp[f];
        float4 kv = *(const float4*)&rowp[512 + f];
        float4 vv = *(const float4*)&rowp[1024 + f];
        *(float2*)&qs[n][f]     = make_float2(qv.x, qv.y);
        *(float2*)&qs[n][f + 2] = make_float2(qv.z, qv.w);
        *(float2*)&ks[n][f]     = make_float2(kv.x, kv.y);
        *(float2*)&ks[n][f + 2] = make_float2(kv.z, kv.w);
        *(float2*)&vs[n][f]     = make_float2(vv.x, vv.y);
        *(float2*)&vs[n][f + 2] = make_float2(vv.z, vv.w);
    }
    float scale = fexp(fminf(logit_scale[h], LOGMAX));
    __syncthreads();

    {
        int r = tid >> 1;
        int half = tid & 1;
        float* row = (r < 64) ? qs[r] : ks[r - 64];
        float ss = 0.f;
        #pragma unroll
        for (int d2 = 0; d2 < 16; d2 += 2) {
            float2 v = *(float2*)&row[half * 16 + d2];
            ss += v.x * v.x + v.y * v.y;
        }
        ss += __shfl_xor_sync(0xffffffffu, ss, 1);
        float inv = rsqrtf(ss);
        if (r < 64) inv *= scale;
        #pragma unroll
        for (int d = 0; d < 16; ++d) row[half * 16 + d] *= inv;
    }
    __syncthreads();

    const int ty = tid >> 4, tx = tid & 15;
    unsigned long long a2[4][4];
    #pragma unroll
    for (int ii = 0; ii < 4; ++ii)
        #pragma unroll
        for (int jj = 0; jj < 4; ++jj) a2[ii][jj] = 0ull;
    #pragma unroll
    for (int d2 = 0; d2 < 16; ++d2) {
        unsigned long long q2[4], k2[4];
        #pragma unroll
        for (int ii = 0; ii < 4; ++ii)
            q2[ii] = *(unsigned long long*)&qs[4 * ty + ii][2 * d2];
        #pragma unroll
        for (int jj = 0; jj < 4; ++jj)
            k2[jj] = *(unsigned long long*)&ks[tx + 16 * jj][2 * d2];
        #pragma unroll
        for (int ii = 0; ii < 4; ++ii)
            #pragma unroll
            for (int jj = 0; jj < 4; ++jj)
                ffma2(a2[ii][jj], q2[ii], k2[jj]);
    }
    const float* bias_h = &g_bias[h * 4096];
    const float* mask_w = &mask[(size_t)(win & (NWMASK - 1)) * 4096];
    float sv[4][4];
    #pragma unroll
    for (int ii = 0; ii < 4; ++ii) {
        int r = 4 * ty + ii;
        #pragma unroll
        for (int jj = 0; jj < 4; ++jj) {
            int c = tx + 16 * jj;
            float x, y;
            unpack2(a2[ii][jj], x, y);
            sv[ii][jj] = x + y + bias_h[r * 64 + c] + mask_w[r * 64 + c];
        }
    }
    float sr[4];
    #pragma unroll
    for (int ii = 0; ii < 4; ++ii) {
        float m = fmaxf(fmaxf(sv[ii][0], sv[ii][1]), fmaxf(sv[ii][2], sv[ii][3]));
        m = fmaxf(m, __shfl_xor_sync(0xffffffffu, m, 1));
        m = fmaxf(m, __shfl_xor_sync(0xffffffffu, m, 2));
        m = fmaxf(m, __shfl_xor_sync(0xffffffffu, m, 4));
        m = fmaxf(m, __shfl_xor_sync(0xffffffffu, m, 8));
        float s = 0.f;
        #pragma unroll
        for (int jj = 0; jj < 4; ++jj) {
            sv[ii][jj] = fexp(sv[ii][jj] - m);
            s += sv[ii][jj];
        }
        s += __shfl_xor_sync(0xffffffffu, s, 1);
        s += __shfl_xor_sync(0xffffffffu, s, 2);
        s += __shfl_xor_sync(0xffffffffu, s, 4);
        s += __shfl_xor_sync(0xffffffffu, s, 8);
        sr[ii] = __frcp_rn(s);
    }
    #pragma unroll
    for (int ii = 0; ii < 4; ++ii)
        #pragma unroll
        for (int jj = 0; jj < 4; ++jj)
            S[4 * ty + ii][tx + 16 * jj] = sv[ii][jj] * sr[ii];
    __syncthreads();

    // PV: pairs of j; p as float2 (S rows 8B-aligned via SP=66)
    const int ti = ty, tu = tx;
    unsigned long long pa[4] = {0ull, 0ull, 0ull, 0ull};
    #pragma unroll 4
    for (int j2 = 0; j2 < 32; ++j2) {
        unsigned long long va = *(unsigned long long*)&vs[2 * j2][2 * tu];
        unsigned long long vb = *(unsigned long long*)&vs[2 * j2 + 1][2 * tu];
        #pragma unroll
        for (int ii = 0; ii < 4; ++ii) {
            float2 p2 = *(float2*)&S[4 * ti + ii][2 * j2];
            ffma2(pa[ii], pack2(p2.x, p2.x), va);
            ffma2(pa[ii], pack2(p2.y, p2.y), vb);
        }
    }
    #pragma unroll
    for (int ii = 0; ii < 4; ++ii) {
        float x, y;
        unpack2(pa[ii], x, y);
        size_t orow = ((size_t)win * 64 + 4 * ti + ii) * CHANS + h * HDIM + 2 * tu;
        __nv_bfloat16 hx, lx, hy, ly;
        split1(x, hx, lx);
        split1(y, hy, ly);
        __nv_bfloat162 hv, lv;
        hv.x = hx; hv.y = hy;
        lv.x = lx; lv.y = ly;
        *(__nv_bfloat162*)&g_ao_hi[orow] = hv;
        *(__nv_bfloat162*)&g_ao_lo[orow] = lv;
    }
}

// ---------------- launch ----------------
extern "C" void kernel_launch(void* const* d_in, const int* in_sizes, int n_in,
                              void* d_out, int out_size) {
    const float* x       = (const float*)d_in[0];
    const float* mask    = (const float*)d_in[1];
    const float* rel_t   = (const float*)d_in[2];
    const float* w_qkv   = (const float*)d_in[3];
    const float* q_bias  = (const float*)d_in[4];
    const float* v_bias  = (const float*)d_in[5];
    const float* lscale  = (const float*)d_in[6];
    const float* cpb_w1  = (const float*)d_in[7];
    const float* cpb_b1  = (const float*)d_in[8];
    const float* cpb_w2  = (const float*)d_in[9];
    const float* proj_w  = (const float*)d_in[10];
    const float* proj_b  = (const float*)d_in[11];
    float* out = (float*)d_out;

    void *p_qkv, *p_qb, *p_xh, *p_xl, *p_aoh, *p_aol, *p_wqh, *p_wql, *p_wph, *p_wpl;
    cudaGetSymbolAddress(&p_qkv, g_qkv);
    cudaGetSymbolAddress(&p_qb, g_qkv_bias);
    cudaGetSymbolAddress(&p_xh, g_x_hi);
    cudaGetSymbolAddress(&p_xl, g_x_lo);
    cudaGetSymbolAddress(&p_aoh, g_ao_hi);
    cudaGetSymbolAddress(&p_aol, g_ao_lo);
    cudaGetSymbolAddress(&p_wqh, g_wq_hi);
    cudaGetSymbolAddress(&p_wql, g_wq_lo);
    cudaGetSymbolAddress(&p_wph, g_wp_hi);
    cudaGetSymbolAddress(&p_wpl, g_wp_lo);

    cudaFuncSetAttribute(hmma_gemm, cudaFuncAttributeMaxDynamicSharedMemorySize, GEMM_SMEM);

    qkvbias_kernel<<<6, 256>>>(q_bias, v_bias);
    cpb_table_kernel<<<225, 512>>>(rel_t, cpb_w1, cpb_b1, cpb_w2);
    bias_expand_kernel<<<256, 256>>>();

    split_x_kernel<<<(MROWS * CHANS) / 1024, 256>>>(x);
    wsplit_kernel<<<(CHANS * QKVN + 255) / 256, 256>>>(
        w_qkv, (__nv_bfloat16*)p_wqh, (__nv_bfloat16*)p_wql, CHANS, QKVN);
    wsplit_kernel<<<(CHANS * CHANS + 255) / 256, 256>>>(
        proj_w, (__nv_bfloat16*)p_wph, (__nv_bfloat16*)p_wpl, CHANS, CHANS);

    // QKV: [131072,512] @ [512,1536]
    hmma_gemm<<<dim3(QKVN / 128, MROWS / 128), 256, GEMM_SMEM>>>(
        (const __nv_bfloat16*)p_xh, (const __nv_bfloat16*)p_xl,
        (const __nv_bfloat16*)p_wqh, (const __nv_bfloat16*)p_wql,
        (const float*)p_qb, (float*)p_qkv, MROWS, QKVN, CHANS);

    attn_kernel<<<dim3(NHEAD, BWIN), 256>>>(mask, lscale);

    // proj: [131072,512] @ [512,512]
    hmma_gemm<<<dim3(CHANS / 128, MROWS / 128), 256, GEMM_SMEM>>>(
        (const __nv_bfloat16*)p_aoh, (const __nv_bfloat16*)p_aol,
        (const __nv_bfloat16*)p_wph, (const __nv_bfloat16*)p_wpl,
        proj_b, out, MROWS, CHANS, CHANS);
}

// round 11
// speedup vs baseline: 1.2390x; 1.0251x over previous
#include <cuda_runtime.h>
#include <cuda_bf16.h>
#include <math.h>
#include <stdint.h>

// ---------------- problem constants ----------------
#define BWIN   2048
#define NTOK   64
#define CHANS  512
#define NHEAD  16
#define HDIM   32
#define NWMASK 256
#define MROWS  (BWIN * NTOK)     // 131072
#define QKVN   (3 * CHANS)       // 1536
#define LOGMAX 4.6051701859880914f

// ---------------- scratch ----------------
__device__ float g_qkv[(size_t)MROWS * QKVN];
__device__ __nv_bfloat16 g_x_hi[(size_t)MROWS * CHANS];
__device__ __nv_bfloat16 g_x_lo[(size_t)MROWS * CHANS];
__device__ __nv_bfloat16 g_ao_hi[(size_t)MROWS * CHANS];
__device__ __nv_bfloat16 g_ao_lo[(size_t)MROWS * CHANS];
__device__ __nv_bfloat16 g_wq_hi[(size_t)QKVN * CHANS];   // [N,K] transposed
__device__ __nv_bfloat16 g_wq_lo[(size_t)QKVN * CHANS];
__device__ __nv_bfloat16 g_wp_hi[(size_t)CHANS * CHANS];
__device__ __nv_bfloat16 g_wp_lo[(size_t)CHANS * CHANS];
__device__ float g_table[225 * NHEAD];
__device__ float g_bm[(size_t)NWMASK * NHEAD * NTOK * NTOK];   // bias+mask combined
__device__ float g_qkv_bias[QKVN];

// ---------------- helpers ----------------
__device__ __forceinline__ uint32_t smem_u32(const void* p) {
    uint32_t a;
    asm("{ .reg .u64 t; cvta.to.shared.u64 t, %1; cvt.u32.u64 %0, t; }" : "=r"(a) : "l"(p));
    return a;
}
__device__ __forceinline__ void cp16(uint32_t dst, const void* src) {
    asm volatile("cp.async.cg.shared.global [%0], [%1], 16;" :: "r"(dst), "l"(src));
}
#define CP_COMMIT() asm volatile("cp.async.commit_group;" ::: "memory")
__device__ __forceinline__ void cp_wait(int rem) {
    if (rem >= 1) asm volatile("cp.async.wait_group 1;" ::: "memory");
    else          asm volatile("cp.async.wait_group 0;" ::: "memory");
}
__device__ __forceinline__ void ldm_x4(uint32_t* r, uint32_t addr) {
    asm volatile("ldmatrix.sync.aligned.m8n8.x4.shared.b16 {%0,%1,%2,%3}, [%4];"
                 : "=r"(r[0]), "=r"(r[1]), "=r"(r[2]), "=r"(r[3]) : "r"(addr));
}
__device__ __forceinline__ void mma_bf16(float* d, const uint32_t* a, uint32_t b0, uint32_t b1) {
    asm volatile(
        "mma.sync.aligned.m16n8k16.row.col.f32.bf16.bf16.f32 "
        "{%0,%1,%2,%3}, {%4,%5,%6,%7}, {%8,%9}, {%0,%1,%2,%3};"
        : "+f"(d[0]), "+f"(d[1]), "+f"(d[2]), "+f"(d[3])
        : "r"(a[0]), "r"(a[1]), "r"(a[2]), "r"(a[3]), "r"(b0), "r"(b1));
}
__device__ __forceinline__ void split1(float x, __nv_bfloat16& h, __nv_bfloat16& l) {
    h = __float2bfloat16(x);
    l = __float2bfloat16(x - __bfloat162float(h));
}
// packed f32x2 FMA (Blackwell FFMA2, PTX-only)
__device__ __forceinline__ void ffma2(unsigned long long& d,
                                      unsigned long long a, unsigned long long b) {
    asm("fma.rn.f32x2 %0, %1, %2, %0;" : "+l"(d) : "l"(a), "l"(b));
}
__device__ __forceinline__ unsigned long long pack2(float x, float y) {
    unsigned long long r;
    asm("mov.b64 %0, {%1, %2};" : "=l"(r) : "f"(x), "f"(y));
    return r;
}
__device__ __forceinline__ void unpack2(unsigned long long v, float& x, float& y) {
    asm("mov.b64 {%0, %1}, %2;" : "=f"(x), "=f"(y) : "l"(v));
}
// fast exp via FMA polynomial (no MUFU)
__device__ __forceinline__ float fexp(float x) {
    float t = fmaxf(x * 1.442695040888963f, -125.f);
    float n = rintf(t);
    float f = t - n;
    float p = 1.3392138e-3f;
    p = fmaf(p, f, 9.6181291e-3f);
    p = fmaf(p, f, 5.5504108e-2f);
    p = fmaf(p, f, 2.4022650e-1f);
    p = fmaf(p, f, 6.9314718e-1f);
    p = fmaf(p, f, 1.0f);
    return __int_as_float(((int)n + 127) << 23) * p;
}

// ---------------- tiny prep kernels ----------------
__global__ void qkvbias_kernel(const float* __restrict__ qb,
                               const float* __restrict__ vb) {
    int n = blockIdx.x * 256 + threadIdx.x;
    if (n >= QKVN) return;
    float v = 0.f;
    if (n < CHANS) v = qb[n];
    else if (n >= 2 * CHANS) v = vb[n - 2 * CHANS];
    g_qkv_bias[n] = v;
}

__global__ void cpb_table_kernel(const float* __restrict__ rel_table,
                                 const float* __restrict__ w1,
                                 const float* __restrict__ b1,
                                 const float* __restrict__ w2) {
    int p = blockIdx.x;
    int j = threadIdx.x;
    __shared__ float hid[512];
    float t0 = rel_table[p * 2 + 0];
    float t1 = rel_table[p * 2 + 1];
    hid[j] = fmaxf(t0 * w1[j] + t1 * w1[512 + j] + b1[j], 0.f);
    __syncthreads();
    if (j < NHEAD) {
        float acc = 0.f;
        #pragma unroll 8
        for (int r = 0; r < 512; ++r) acc += hid[r] * w2[r * NHEAD + j];
        g_table[p * NHEAD + j] = acc;
    }
}

// g_bm[nw][h][i][j] = 16*sigmoid(table[idx(i,j)][h]) + mask[nw][i][j]
__global__ void bm_expand_kernel(const float* __restrict__ mask) {
    size_t id = (size_t)blockIdx.x * 256 + threadIdx.x;   // 16.7M
    int nw = (int)(id >> 16);
    int h = (int)(id >> 12) & 15;
    int i = (int)(id >> 6) & 63;
    int j = (int)id & 63;
    int idx = ((i >> 3) - (j >> 3) + 7) * 15 + ((i & 7) - (j & 7) + 7);
    float b = g_table[idx * NHEAD + h];
    g_bm[id] = 16.f / (1.f + fexp(-b)) + mask[(size_t)nw * 4096 + i * 64 + j];
}

__global__ void split_x_kernel(const float* __restrict__ src) {
    size_t i = ((size_t)blockIdx.x * 256 + threadIdx.x) * 4;
    float4 v = *(const float4*)&src[i];
    __align__(8) __nv_bfloat16 h[4], l[4];
    split1(v.x, h[0], l[0]);
    split1(v.y, h[1], l[1]);
    split1(v.z, h[2], l[2]);
    split1(v.w, h[3], l[3]);
    *(uint2*)&g_x_hi[i] = *(uint2*)h;
    *(uint2*)&g_x_lo[i] = *(uint2*)l;
}

__global__ void wsplit_kernel(const float* __restrict__ w,
                              __nv_bfloat16* __restrict__ hiT,
                              __nv_bfloat16* __restrict__ loT,
                              int K, int N) {
    int idx = blockIdx.x * 256 + threadIdx.x;
    if (idx >= K * N) return;
    int k = idx / N, n = idx % N;
    __nv_bfloat16 h, l;
    split1(w[idx], h, l);
    hiT[(size_t)n * K + k] = h;
    loT[(size_t)n * K + k] = l;
}

// ---------------- HMMA bf16x3 GEMM ----------------
// C[M,N] = (Ahi+Alo)[M,K] @ (Bhi+Blo)[N,K]^T + bias[N]
// BM=128 BN=128 BK=32, 256 thr / 8 warps (2Mx4N), warp tile 64x32,
// XOR-swizzled 64B rows, 3-stage cp.async, one barrier per chunk,
// cp.async issue DEFERRED into the first MMA block of the chunk.
#define TILE_B 8192                      // 128 rows x 64 B
#define STAGE_B (4 * TILE_B)             // 32768 B
#define NSTAGE 3
#define GEMM_SMEM (NSTAGE * STAGE_B)     // 98304 B

__device__ __forceinline__ uint32_t swz(uint32_t tile, int row, int chunk) {
    return tile + row * 64 + (((chunk + (row >> 1)) & 3) << 4);
}

__global__ void __launch_bounds__(256, 2)
hmma_gemm(const __nv_bfloat16* __restrict__ Ahi, const __nv_bfloat16* __restrict__ Alo,
          const __nv_bfloat16* __restrict__ Bhi, const __nv_bfloat16* __restrict__ Blo,
          const float* __restrict__ bias, float* __restrict__ C,
          int M, int N, int K) {
    extern __shared__ char smem[];
    const uint32_t sb = smem_u32(smem);
    const int tid = threadIdx.x;
    const int wid = tid >> 5, lane = tid & 31;
    const int bm = blockIdx.y * 128;
    const int bn = blockIdx.x * 128;
    const int wm = (wid >> 2) * 64;
    const int wn = (wid & 3) * 32;
    const int nch = K >> 5;

    auto load_tile = [&](const __nv_bfloat16* g, int rowbase, int k0, uint32_t off) {
        #pragma unroll
        for (int c = tid; c < 512; c += 256) {
            int row = c >> 2, chunk = c & 3;
            cp16(swz(sb + off, row, chunk),
                 g + (size_t)(rowbase + row) * K + k0 + chunk * 8);
        }
    };
    auto load_chunk = [&](int chunk) {
        int k0 = chunk << 5;
        uint32_t s0 = (uint32_t)(chunk % NSTAGE) * STAGE_B;
        load_tile(Ahi, bm, k0, s0);
        load_tile(Alo, bm, k0, s0 + TILE_B);
        load_tile(Bhi, bn, k0, s0 + 2 * TILE_B);
        load_tile(Blo, bn, k0, s0 + 3 * TILE_B);
        CP_COMMIT();
    };

    float acc[4][4][4] = {};

    load_chunk(0);
    if (nch > 1) load_chunk(1);

    const int lt = lane >> 3;
    const int lr = lane & 7;
    const int a_row_in = ((lt & 1) << 3) + lr;
    const int a_k16 = lt >> 1;
    const int b_n_in = ((lt >> 1) << 3) + lr;
    const int b_k16 = lt & 1;

    for (int i = 0; i < nch; ++i) {
        cp_wait(i + 1 < nch ? 1 : 0);
        __syncthreads();

        const uint32_t s0 = sb + (uint32_t)(i % NSTAGE) * STAGE_B;
        #pragma unroll
        for (int ks = 0; ks < 2; ++ks) {
            uint32_t afh[4][4], bfh[2][4], tf[4][4];
            const int ck = ks * 2;
            // A hi frags (m64)
            #pragma unroll
            for (int mi = 0; mi < 4; ++mi)
                ldm_x4(afh[mi], swz(s0, wm + mi * 16 + a_row_in, ck + a_k16));
            // B hi frags (n32)
            #pragma unroll
            for (int ni = 0; ni < 2; ++ni)
                ldm_x4(bfh[ni], swz(s0 + 2 * TILE_B, wn + ni * 16 + b_n_in, ck + b_k16));
            // hi*hi
            #pragma unroll
            for (int mi = 0; mi < 4; ++mi)
                #pragma unroll
                for (int nj = 0; nj < 4; ++nj)
                    mma_bf16(acc[mi][nj], afh[mi], bfh[nj >> 1][(nj & 1) * 2],
                             bfh[nj >> 1][(nj & 1) * 2 + 1]);
            // deferred global prefetch of chunk i+2: tensor pipe is busy now
            if (ks == 0 && i + 2 < nch) load_chunk(i + 2);
            // B lo frags -> hi*lo
            #pragma unroll
            for (int ni = 0; ni < 2; ++ni)
                ldm_x4(tf[ni], swz(s0 + 3 * TILE_B, wn + ni * 16 + b_n_in, ck + b_k16));
            #pragma unroll
            for (int mi = 0; mi < 4; ++mi)
                #pragma unroll
                for (int nj = 0; nj < 4; ++nj)
                    mma_bf16(acc[mi][nj], afh[mi], tf[nj >> 1][(nj & 1) * 2],
                             tf[nj >> 1][(nj & 1) * 2 + 1]);
            // A lo frags -> lo*hi
            #pragma unroll
            for (int mi = 0; mi < 4; ++mi)
                ldm_x4(tf[mi], swz(s0 + TILE_B, wm + mi * 16 + a_row_in, ck + a_k16));
            #pragma unroll
            for (int mi = 0; mi < 4; ++mi)
                #pragma unroll
                for (int nj = 0; nj < 4; ++nj)
                    mma_bf16(acc[mi][nj], tf[mi], bfh[nj >> 1][(nj & 1) * 2],
                             bfh[nj >> 1][(nj & 1) * 2 + 1]);
        }
    }

    const int er = lane >> 2;
    const int ec = (lane & 3) * 2;
    #pragma unroll
    for (int mi = 0; mi < 4; ++mi) {
        #pragma unroll
        for (int nj = 0; nj < 4; ++nj) {
            int col = bn + wn + nj * 8 + ec;
            float b0 = bias[col], b1 = bias[col + 1];
            int r0 = bm + wm + mi * 16 + er;
            float2 v0 = make_float2(acc[mi][nj][0] + b0, acc[mi][nj][1] + b1);
            float2 v1 = make_float2(acc[mi][nj][2] + b0, acc[mi][nj][3] + b1);
            *(float2*)&C[(size_t)r0 * N + col] = v0;
            *(float2*)&C[(size_t)(r0 + 8) * N + col] = v1;
        }
    }
}

// ---------------- attention: blocked f32x2, one CTA per (head, window) ----
#define QKP 34
#define SP  66   // S row stride (even -> float2-aligned rows)
__global__ __launch_bounds__(256)
void attn_kernel(const float* __restrict__ logit_scale) {
    const int h = blockIdx.x;
    const int win = blockIdx.y;
    __shared__ float qs[64][QKP];
    __shared__ float ks[64][QKP];
    __shared__ float vs[64][QKP];
    __shared__ float S[64][SP];
    const int tid = threadIdx.x;

    const size_t base = (size_t)win * 64 * QKVN + h * HDIM;
    #pragma unroll
    for (int l = 0; l < 2; ++l) {
        int t = tid + l * 256;
        int n = t >> 3;
        int f = (t & 7) << 2;
        const float* rowp = &g_qkv[base + (size_t)n * QKVN];
        float4 qv = *(const float4*)&rowp[f];
        float4 kv = *(const float4*)&rowp[512 + f];
        float4 vv = *(const float4*)&rowp[1024 + f];
        *(float2*)&qs[n][f]     = make_float2(qv.x, qv.y);
        *(float2*)&qs[n][f + 2] = make_float2(qv.z, qv.w);
        *(float2*)&ks[n][f]     = make_float2(kv.x, kv.y);
        *(float2*)&ks[n][f + 2] = make_float2(kv.z, kv.w);
        *(float2*)&vs[n][f]     = make_float2(vv.x, vv.y);
        *(float2*)&vs[n][f + 2] = make_float2(vv.z, vv.w);
    }
    float scale = fexp(fminf(logit_scale[h], LOGMAX));
    __syncthreads();

    {
        int r = tid >> 1;
        int half = tid & 1;
        float* row = (r < 64) ? qs[r] : ks[r - 64];
        float ss = 0.f;
        #pragma unroll
        for (int d2 = 0; d2 < 16; d2 += 2) {
            float2 v = *(float2*)&row[half * 16 + d2];
            ss += v.x * v.x + v.y * v.y;
        }
        ss += __shfl_xor_sync(0xffffffffu, ss, 1);
        float inv = rsqrtf(ss);
        if (r < 64) inv *= scale;
        #pragma unroll
        for (int d = 0; d < 16; ++d) row[half * 16 + d] *= inv;
    }
    __syncthreads();

    const int ty = tid >> 4, tx = tid & 15;
    unsigned long long a2[4][4];
    #pragma unroll
    for (int ii = 0; ii < 4; ++ii)
        #pragma unroll
        for (int jj = 0; jj < 4; ++jj) a2[ii][jj] = 0ull;
    #pragma unroll
    for (int d2 = 0; d2 < 16; ++d2) {
        unsigned long long q2[4], k2[4];
        #pragma unroll
        for (int ii = 0; ii < 4; ++ii)
            q2[ii] = *(unsigned long long*)&qs[4 * ty + ii][2 * d2];
        #pragma unroll
        for (int jj = 0; jj < 4; ++jj)
            k2[jj] = *(unsigned long long*)&ks[tx + 16 * jj][2 * d2];
        #pragma unroll
        for (int ii = 0; ii < 4; ++ii)
            #pragma unroll
            for (int jj = 0; jj < 4; ++jj)
                ffma2(a2[ii][jj], q2[ii], k2[jj]);
    }
    const float* bm = &g_bm[(size_t)((win & (NWMASK - 1)) * NHEAD + h) * 4096];
    float sv[4][4];
    #pragma unroll
    for (int ii = 0; ii < 4; ++ii) {
        int r = 4 * ty + ii;
        #pragma unroll
        for (int jj = 0; jj < 4; ++jj) {
            int c = tx + 16 * jj;
            float x, y;
            unpack2(a2[ii][jj], x, y);
            sv[ii][jj] = x + y + bm[r * 64 + c];
        }
    }
    float sr[4];
    #pragma unroll
    for (int ii = 0; ii < 4; ++ii) {
        float m = fmaxf(fmaxf(sv[ii][0], sv[ii][1]), fmaxf(sv[ii][2], sv[ii][3]));
        m = fmaxf(m, __shfl_xor_sync(0xffffffffu, m, 1));
        m = fmaxf(m, __shfl_xor_sync(0xffffffffu, m, 2));
        m = fmaxf(m, __shfl_xor_sync(0xffffffffu, m, 4));
        m = fmaxf(m, __shfl_xor_sync(0xffffffffu, m, 8));
        float s = 0.f;
        #pragma unroll
        for (int jj = 0; jj < 4; ++jj) {
            sv[ii][jj] = fexp(sv[ii][jj] - m);
            s += sv[ii][jj];
        }
        s += __shfl_xor_sync(0xffffffffu, s, 1);
        s += __shfl_xor_sync(0xffffffffu, s, 2);
        s += __shfl_xor_sync(0xffffffffu, s, 4);
        s += __shfl_xor_sync(0xffffffffu, s, 8);
        sr[ii] = __frcp_rn(s);
    }
    #pragma unroll
    for (int ii = 0; ii < 4; ++ii)
        #pragma unroll
        for (int jj = 0; jj < 4; ++jj)
            S[4 * ty + ii][tx + 16 * jj] = sv[ii][jj] * sr[ii];
    __syncthreads();

    // PV: pairs of j; p as float2 (S rows 8B-aligned via SP=66)
    const int ti = ty, tu = tx;
    unsigned long long pa[4] = {0ull, 0ull, 0ull, 0ull};
    #pragma unroll 4
    for (int j2 = 0; j2 < 32; ++j2) {
        unsigned long long va = *(unsigned long long*)&vs[2 * j2][2 * tu];
        unsigned long long vb = *(unsigned long long*)&vs[2 * j2 + 1][2 * tu];
        #pragma unroll
        for (int ii = 0; ii < 4; ++ii) {
            float2 p2 = *(float2*)&S[4 * ti + ii][2 * j2];
            ffma2(pa[ii], pack2(p2.x, p2.x), va);
            ffma2(pa[ii], pack2(p2.y, p2.y), vb);
        }
    }
    #pragma unroll
    for (int ii = 0; ii < 4; ++ii) {
        float x, y;
        unpack2(pa[ii], x, y);
        size_t orow = ((size_t)win * 64 + 4 * ti + ii) * CHANS + h * HDIM + 2 * tu;
        __nv_bfloat16 hx, lx, hy, ly;
        split1(x, hx, lx);
        split1(y, hy, ly);
        __nv_bfloat162 hv, lv;
        hv.x = hx; hv.y = hy;
        lv.x = lx; lv.y = ly;
        *(__nv_bfloat162*)&g_ao_hi[orow] = hv;
        *(__nv_bfloat162*)&g_ao_lo[orow] = lv;
    }
}

// ---------------- launch ----------------
extern "C" void kernel_launch(void* const* d_in, const int* in_sizes, int n_in,
                              void* d_out, int out_size) {
    const float* x       = (const float*)d_in[0];
    const float* mask    = (const float*)d_in[1];
    const float* rel_t   = (const float*)d_in[2];
    const float* w_qkv   = (const float*)d_in[3];
    const float* q_bias  = (const float*)d_in[4];
    const float* v_bias  = (const float*)d_in[5];
    const float* lscale  = (const float*)d_in[6];
    const float* cpb_w1  = (const float*)d_in[7];
    const float* cpb_b1  = (const float*)d_in[8];
    const float* cpb_w2  = (const float*)d_in[9];
    const float* proj_w  = (const float*)d_in[10];
    const float* proj_b  = (const float*)d_in[11];
    float* out = (float*)d_out;

    void *p_qkv, *p_qb, *p_xh, *p_xl, *p_aoh, *p_aol, *p_wqh, *p_wql, *p_wph, *p_wpl;
    cudaGetSymbolAddress(&p_qkv, g_qkv);
    cudaGetSymbolAddress(&p_qb, g_qkv_bias);
    cudaGetSymbolAddress(&p_xh, g_x_hi);
    cudaGetSymbolAddress(&p_xl, g_x_lo);
    cudaGetSymbolAddress(&p_aoh, g_ao_hi);
    cudaGetSymbolAddress(&p_aol, g_ao_lo);
    cudaGetSymbolAddress(&p_wqh, g_wq_hi);
    cudaGetSymbolAddress(&p_wql, g_wq_lo);
    cudaGetSymbolAddress(&p_wph, g_wp_hi);
    cudaGetSymbolAddress(&p_wpl, g_wp_lo);

    cudaFuncSetAttribute(hmma_gemm, cudaFuncAttributeMaxDynamicSharedMemorySize, GEMM_SMEM);

    qkvbias_kernel<<<6, 256>>>(q_bias, v_bias);
    cpb_table_kernel<<<225, 512>>>(rel_t, cpb_w1, cpb_b1, cpb_w2);
    bm_expand_kernel<<<65536, 256>>>(mask);

    split_x_kernel<<<(MROWS * CHANS) / 1024, 256>>>(x);
    wsplit_kernel<<<(CHANS * QKVN + 255) / 256, 256>>>(
        w_qkv, (__nv_bfloat16*)p_wqh, (__nv_bfloat16*)p_wql, CHANS, QKVN);
    wsplit_kernel<<<(CHANS * CHANS + 255) / 256, 256>>>(
        proj_w, (__nv_bfloat16*)p_wph, (__nv_bfloat16*)p_wpl, CHANS, CHANS);

    // QKV: [131072,512] @ [512,1536]
    hmma_gemm<<<dim3(QKVN / 128, MROWS / 128), 256, GEMM_SMEM>>>(
        (const __nv_bfloat16*)p_xh, (const __nv_bfloat16*)p_xl,
        (const __nv_bfloat16*)p_wqh, (const __nv_bfloat16*)p_wql,
        (const float*)p_qb, (float*)p_qkv, MROWS, QKVN, CHANS);

    attn_kernel<<<dim3(NHEAD, BWIN), 256>>>(lscale);

    // proj: [131072,512] @ [512,512]
    hmma_gemm<<<dim3(CHANS / 128, MROWS / 128), 256, GEMM_SMEM>>>(
        (const __nv_bfloat16*)p_aoh, (const __nv_bfloat16*)p_aol,
        (const __nv_bfloat16*)p_wph, (const __nv_bfloat16*)p_wpl,
        proj_b, out, MROWS, CHANS, CHANS);
}